// round 7
// baseline (speedup 1.0000x reference)
#include <cuda_runtime.h>
#include <cuda_fp16.h>
#include <cstdint>

#define Bn   2
#define Nn   2048
#define CIN  128
#define Hh   16
#define Cc   8
#define HC   128
#define LOG2E 1.4426950408889634f
#define NJB  16          // j-blocks of 128

// dynamic smem (halves): H tiles 2x16384, adj tiles 2x2048
#define SH_H   16384
#define SH_A   2048
#define SMEM_HALVES (2 * SH_H + 2 * SH_A)
#define SMEM_BYTES  (SMEM_HALVES * 2)
#define TILE_BYTES  (SH_H * 2 + SH_A * 2)   // 36864 per buffer

// ---- device scratch (pre-swizzled layouts) ----
__device__ __half   g_adjh[Bn * Nn * Nn];  // fp16 adj, chunk^(row&7) swizzled per 128-col block
__device__ __half   g_hT [Bn * HC * Nn];   // [b][f][n] fp16, chunk^(f&7) swizzled per 128-n block
__device__ float    g_lp [Bn * Nn * Hh];   // lp * log2e
__device__ __half2  g_FF [Bn * Hh * Nn];   // (2^lc, 2^(0.2lc)) per node
__device__ unsigned g_mxu[Bn * Hh];        // encoded max_j lc'

// ---- PTX helpers ----
static __device__ __forceinline__ uint32_t s2u(const void* p) {
    return (uint32_t)__cvta_generic_to_shared(p);
}
static __device__ __forceinline__ float ex2f(float x) {
    float r; asm("ex2.approx.f32 %0, %1;" : "=f"(r) : "f"(x)); return r;
}
static __device__ __forceinline__ uint32_t prmtb(uint32_t a, uint32_t b, uint32_t sel) {
    uint32_t d; asm("prmt.b32 %0, %1, %2, %3;" : "=r"(d) : "r"(a), "r"(b), "r"(sel)); return d;
}
static __device__ __forceinline__ uint32_t h2b(__half2 v) {
    return *reinterpret_cast<uint32_t*>(&v);
}
static __device__ __forceinline__ __half2 b2h(uint32_t u) {
    return *reinterpret_cast<__half2*>(&u);
}
static __device__ __forceinline__ unsigned encf(float f) {
    int i = __float_as_int(f);
    return (i >= 0) ? ((unsigned)i | 0x80000000u) : ~(unsigned)i;
}
static __device__ __forceinline__ float decf(unsigned u) {
    int i = (u & 0x80000000u) ? (int)(u & 0x7FFFFFFFu) : (int)~u;
    return __int_as_float(i);
}
static __device__ __forceinline__ void mma16816(float& d0, float& d1, float& d2, float& d3,
                                                uint32_t a0, uint32_t a1, uint32_t a2, uint32_t a3,
                                                uint32_t b0, uint32_t b1) {
    asm("mma.sync.aligned.m16n8k16.row.col.f32.f16.f16.f32 "
        "{%0,%1,%2,%3}, {%4,%5,%6,%7}, {%8,%9}, {%0,%1,%2,%3};"
        : "+f"(d0), "+f"(d1), "+f"(d2), "+f"(d3)
        : "r"(a0), "r"(a1), "r"(a2), "r"(a3), "r"(b0), "r"(b1));
}
#define MBAR_INIT(mb, cnt) \
    asm volatile("mbarrier.init.shared.b64 [%0], %1;" :: "r"(mb), "r"(cnt) : "memory")
#define MBAR_EXPECT(mb, bytes) \
    asm volatile("mbarrier.arrive.expect_tx.shared.b64 _, [%0], %1;" :: "r"(mb), "r"(bytes) : "memory")
#define BLKCP(dst, src, bytes, mb) \
    asm volatile("cp.async.bulk.shared::cta.global.mbarrier::complete_tx::bytes [%0], [%1], %2, [%3];" \
                 :: "r"(dst), "l"(src), "r"(bytes), "r"(mb) : "memory")
static __device__ __forceinline__ void mbar_wait(uint32_t mb, uint32_t parity) {
    asm volatile(
        "{\n\t.reg .pred P;\n\t"
        "WL_%=:\n\t"
        "mbarrier.try_wait.parity.acquire.cta.shared::cta.b64 P, [%0], %1, 0x989680;\n\t"
        "@P bra.uni WD_%=;\n\t"
        "bra.uni WL_%=;\n\t"
        "WD_%=:\n\t}"
        :: "r"(mb), "r"(parity) : "memory");
}

// ---------------------------------------------------------------
// Kernel A: adj fp32 -> fp16 (chunk-swizzled) + fp32 out-tail copy.
// Each thread: 8 consecutive j (one 16B chunk).
// ---------------------------------------------------------------
__global__ __launch_bounds__(256) void k_adj(const float* __restrict__ adj,
                                             float* __restrict__ out_tail,
                                             int copy_adj) {
    if (blockIdx.x == 0 && threadIdx.x < Bn * Hh)
        g_mxu[threadIdx.x] = 0u;
    const size_t i8 = ((size_t)blockIdx.x * 256 + threadIdx.x) * 8;
    const float4 v0 = *(const float4*)(adj + i8);
    const float4 v1 = *(const float4*)(adj + i8 + 4);
    __half hv[8];
    hv[0] = __float2half(v0.x); hv[1] = __float2half(v0.y);
    hv[2] = __float2half(v0.z); hv[3] = __float2half(v0.w);
    hv[4] = __float2half(v1.x); hv[5] = __float2half(v1.y);
    hv[6] = __float2half(v1.z); hv[7] = __float2half(v1.w);

    const size_t r = i8 >> 11;              // global row (incl. batch)
    const int    j = (int)(i8 & (Nn - 1));
    const int    c = (j & 127) >> 3;        // chunk within 128-block
    const size_t base = (r << 11) + (size_t)(j & ~127);
    *(uint4*)(g_adjh + base + ((c ^ ((int)r & 7)) << 3)) = *(const uint4*)hv;

    if (copy_adj) {
        *(float4*)(out_tail + i8)     = v0;
        *(float4*)(out_tail + i8 + 4) = v1;
    }
}

// ---------------------------------------------------------------
// Kernel B: projection + per-node logits, fused. hT written swizzled.
// ---------------------------------------------------------------
__global__ __launch_bounds__(128) void k_proj(const float* __restrict__ nf,
                                              const float* __restrict__ W,
                                              const float* __restrict__ bias,
                                              const float* __restrict__ a) {
    __shared__ float snf[16][132];
    __shared__ float sred[Hh][17];
    const int t  = threadIdx.x;
    const int r0 = blockIdx.x * 16;
#pragma unroll
    for (int r = 0; r < 16; ++r)
        snf[r][t] = nf[(size_t)(r0 + r) * CIN + t];
    __syncthreads();

    float acc[16];
    const float bv = bias[t];
#pragma unroll
    for (int r = 0; r < 16; ++r) acc[r] = bv;

    for (int k4 = 0; k4 < CIN / 4; ++k4) {
        const float w0 = W[(k4 * 4 + 0) * HC + t];
        const float w1 = W[(k4 * 4 + 1) * HC + t];
        const float w2 = W[(k4 * 4 + 2) * HC + t];
        const float w3 = W[(k4 * 4 + 3) * HC + t];
#pragma unroll
        for (int r = 0; r < 16; ++r) {
            const float4 s = *(const float4*)&snf[r][k4 * 4];
            acc[r] = fmaf(s.x, w0, acc[r]);
            acc[r] = fmaf(s.y, w1, acc[r]);
            acc[r] = fmaf(s.z, w2, acc[r]);
            acc[r] = fmaf(s.w, w3, acc[r]);
        }
    }

    const int b  = r0 >> 11;
    const int n0 = r0 & (Nn - 1);

    // hT write: thread t == feature f; 16 consecutive n = 2 swizzled chunks.
    {
        __half hv[16];
#pragma unroll
        for (int r = 0; r < 16; ++r) hv[r] = __float2half(acc[r]);
        const int c = (n0 & 127) >> 3;             // even chunk
        __half* base = g_hT + ((size_t)b * HC + t) * Nn + (n0 & ~127);
        *(uint4*)(base + ((c       ^ (t & 7)) << 3)) = *(const uint4*)&hv[0];
        *(uint4*)(base + (((c + 1) ^ (t & 7)) << 3)) = *(const uint4*)&hv[8];
    }

    __syncthreads();
#pragma unroll
    for (int r = 0; r < 16; ++r)
        snf[r][t] = acc[r];                // snf now holds h
    __syncthreads();

    const int rr = t >> 3;
    const int hb = (t & 7) * 2;
#pragma unroll
    for (int p = 0; p < 2; ++p) {
        const int h = hb + p;
        const float* hv = &snf[rr][h * Cc];
        const float* ap = a + h * 2 * Cc;
        float lp = 0.f, lc = 0.f;
#pragma unroll
        for (int c = 0; c < Cc; ++c) {
            lp = fmaf(hv[c], ap[c],      lp);
            lc = fmaf(hv[c], ap[Cc + c], lc);
        }
        lp *= LOG2E; lc *= LOG2E;
        const int n = r0 + rr;
        g_lp[n * Hh + h] = lp;
        g_FF[((size_t)b * Hh + h) * Nn + (n & (Nn - 1))] =
            __halves2half2(__float2half(ex2f(lc)), __float2half(ex2f(0.2f * lc)));
        sred[h][rr] = lc;
    }
    __syncthreads();
    if (t < Hh) {
        float m = sred[t][0];
#pragma unroll
        for (int r = 1; r < 16; ++r) m = fmaxf(m, sred[t][r]);
        atomicMax(&g_mxu[b * Hh + t], encf(m));
    }
}

// ---------------------------------------------------------------
// Kernel C: fused softmax-attention via mma.m16n8k16.
// Tiles staged via cp.async.bulk + mbarrier (144 bulk ops per j-block,
// warp0 only). Global layouts pre-swizzled -> conflict-free LDS.
// ---------------------------------------------------------------
__global__ __launch_bounds__(512, 2) void k_main(float* __restrict__ out) {
    extern __shared__ __align__(16) __half smem[];
    __shared__ __align__(8) unsigned long long mbar[2];
    __half* const sH[2] = { smem, smem + SH_H };
    __half* const sA[2] = { smem + 2 * SH_H, smem + 2 * SH_H + SH_A };

    const int t    = threadIdx.x;
    const int warp = t >> 5;
    const int lane = t & 31;
    const int gid  = lane >> 2;   // 0..7
    const int tig  = lane & 3;    // 0..3
    const int hh   = warp;

    const int b  = blockIdx.x >> 7;
    const int i0 = (blockIdx.x & 127) * 16;
    const size_t bN = (size_t)b * Nn;

    const __half* hTb  = g_hT + (size_t)b * HC * Nn;
    const __half* adjh = g_adjh + (bN + i0) * (size_t)Nn;

    // ---- mbarrier init ----
    if (t == 0) { MBAR_INIT(s2u(&mbar[0]), 1); MBAR_INIT(s2u(&mbar[1]), 1); }
    asm volatile("fence.proxy.async.shared::cta;" ::: "memory");
    __syncthreads();

    auto issue_tile = [&](int jb, int bufi) {
        const uint32_t mb = s2u(&mbar[bufi]);
        if (lane == 0) MBAR_EXPECT(mb, TILE_BYTES);
        __syncwarp();
#pragma unroll
        for (int q = 0; q < 4; ++q) {
            const int f = q * 32 + lane;
            BLKCP(s2u(sH[bufi] + f * 128), hTb + (size_t)f * Nn + jb * 128, 256, mb);
        }
        if (lane < 16)
            BLKCP(s2u(sA[bufi] + lane * 128), adjh + (size_t)lane * Nn + jb * 128, 256, mb);
    };

    // per-row factors E = 2^(lp-m), E' = 2^(0.2lp-m)
    __half2 E0, E0p, E1, E1p;
    {
        const float mx  = decf(g_mxu[b * Hh + hh]);
        const float lp0 = g_lp[(bN + i0 + gid)     * Hh + hh];
        const float lp1 = g_lp[(bN + i0 + gid + 8) * Hh + hh];
        const float s0 = lp0 + mx, s1 = lp1 + mx;
        const float m0 = fmaxf(s0, 0.2f * s0);
        const float m1 = fmaxf(s1, 0.2f * s1);
        E0  = __float2half2_rn(ex2f(lp0 - m0));
        E0p = __float2half2_rn(ex2f(0.2f * lp0 - m0));
        E1  = __float2half2_rn(ex2f(lp1 - m1));
        E1p = __float2half2_rn(ex2f(0.2f * lp1 - m1));
    }

    const __half2* FFb = g_FF + ((size_t)b * Hh + hh) * Nn;

    float dn0 = 0.f, dn1 = 0.f, dn2 = 0.f, dn3 = 0.f;
    float dd0 = 0.f, dd1 = 0.f, dd2 = 0.f, dd3 = 0.f;
    const uint32_t ONES = 0x3C003C00u;

    if (warp == 0) issue_tile(0, 0);

    for (int jb = 0; jb < NJB; ++jb) {
        __syncthreads();                       // prior reads of next buffer done
        if (jb + 1 < NJB && warp == 0) issue_tile(jb + 1, (jb + 1) & 1);
        mbar_wait(s2u(&mbar[jb & 1]), (jb >> 1) & 1);

        const __half* hbuf = sH[jb & 1];
        const __half* abuf = sA[jb & 1];
        const __half* Hrow  = hbuf + (hh * 8 + gid) * 128 + 2 * tig;
        const __half* arow0 = abuf + gid * 128       + 2 * tig;
        const __half* arow1 = abuf + (gid + 8) * 128 + 2 * tig;

#pragma unroll 2
        for (int ks = 0; ks < 8; ++ks) {
            const int j  = jb * 128 + ks * 16 + 2 * tig;
            const int c0 = ((2 * ks)     ^ gid) << 3;    // swizzled chunk offsets
            const int c1 = ((2 * ks + 1) ^ gid) << 3;

            const uint2 ffl = *(const uint2*)(FFb + j);
            const uint2 ffh = *(const uint2*)(FFb + j + 8);
            const uint32_t F0  = prmtb(ffl.x, ffl.y, 0x5410);
            const uint32_t Fp0 = prmtb(ffl.x, ffl.y, 0x7632);
            const uint32_t F1  = prmtb(ffh.x, ffh.y, 0x5410);
            const uint32_t Fp1 = prmtb(ffh.x, ffh.y, 0x7632);

            const uint32_t bh0 = *(const uint32_t*)(Hrow + c0);
            const uint32_t bh1 = *(const uint32_t*)(Hrow + c1);

            const __half2 m00 = *(const __half2*)(arow0 + c0);
            const __half2 m01 = *(const __half2*)(arow0 + c1);
            const __half2 m10 = *(const __half2*)(arow1 + c0);
            const __half2 m11 = *(const __half2*)(arow1 + c1);

            const __half2 w0lo = __hmax2(__hmul2(b2h(F0),  E0),  __hmul2(b2h(Fp0), E0p));
            const __half2 w1lo = __hmax2(__hmul2(b2h(F0),  E1),  __hmul2(b2h(Fp0), E1p));
            const __half2 w0hi = __hmax2(__hmul2(b2h(F1),  E0),  __hmul2(b2h(Fp1), E0p));
            const __half2 w1hi = __hmax2(__hmul2(b2h(F1),  E1),  __hmul2(b2h(Fp1), E1p));

            const uint32_t ra0 = h2b(__hmul2(w0lo, m00));
            const uint32_t ra1 = h2b(__hmul2(w1lo, m10));
            const uint32_t ra2 = h2b(__hmul2(w0hi, m01));
            const uint32_t ra3 = h2b(__hmul2(w1hi, m11));

            mma16816(dn0, dn1, dn2, dn3, ra0, ra1, ra2, ra3, bh0, bh1);
            mma16816(dd0, dd1, dd2, dd3, ra0, ra1, ra2, ra3, ONES, ONES);
        }
    }

    // ---- epilogue: divide and store ----
    {
        const float inv0 = 1.0f / dd0;
        const float inv1 = 1.0f / dd2;
        float2 o0 = make_float2(dn0 * inv0, dn1 * inv0);
        float2 o1 = make_float2(dn2 * inv1, dn3 * inv1);
        *(float2*)(out + (bN + i0 + gid)     * HC + hh * Cc + 2 * tig) = o0;
        *(float2*)(out + (bN + i0 + gid + 8) * HC + hh * Cc + 2 * tig) = o1;
    }
}

// ---------------------------------------------------------------
extern "C" void kernel_launch(void* const* d_in, const int* in_sizes, int n_in,
                              void* d_out, int out_size) {
    const float* nf   = (const float*)d_in[0];
    const float* adj  = (const float*)d_in[1];
    const float* W    = (const float*)d_in[2];
    const float* bias = (const float*)d_in[3];
    const float* a    = (const float*)d_in[4];
    float* out = (float*)d_out;

    const long long outel = (long long)Bn * Nn * HC;        // 524288
    const long long adjel = (long long)Bn * Nn * Nn;        // 8388608
    const int copy_adj = ((long long)out_size >= outel + adjel) ? 1 : 0;

    cudaFuncSetAttribute(k_main, cudaFuncAttributeMaxDynamicSharedMemorySize,
                         SMEM_BYTES);

    k_adj <<<(int)(adjel / 2048), 256>>>(adj, out + outel, copy_adj);
    k_proj<<<Bn * Nn / 16, 128>>>(nf, W, bias, a);
    k_main<<<Bn * (Nn / 16), 512, SMEM_BYTES>>>(out);
}

// round 9
// speedup vs baseline: 2.0019x; 2.0019x over previous
#include <cuda_runtime.h>
#include <cuda_fp16.h>
#include <cuda.h>
#include <cstdint>

#define Bn   2
#define Nn   2048
#define CIN  128
#define Hh   16
#define Cc   8
#define HC   128
#define LOG2E 1.4426950408889634f
#define NJB  16          // j-blocks of 128

// dynamic smem (halves): H tiles 2x16384, adj tiles 2x2048
#define SH_H   16384
#define SH_A   2048
#define SMEM_HALVES (2 * SH_H + 2 * SH_A)
#define SMEM_BYTES  (SMEM_HALVES * 2)
#define TILE_BYTES  (SH_H * 2 + SH_A * 2)   // 36864 per buffer

// driver-API typedef (not provided by this toolchain's cudaTypedefs.h)
typedef CUresult (*PFN_tmencode)(
    CUtensorMap*, CUtensorMapDataType, cuuint32_t, void*,
    const cuuint64_t*, const cuuint64_t*, const cuuint32_t*, const cuuint32_t*,
    CUtensorMapInterleave, CUtensorMapSwizzle, CUtensorMapL2promotion,
    CUtensorMapFloatOOBfill);

// ---- device scratch (pre-swizzled layouts, TMA-copied verbatim) ----
__device__ __half   g_adjh[Bn * Nn * Nn];  // fp16 adj, chunk^(row&7) swizzle per 128-col block
__device__ __half   g_hT [Bn * HC * Nn];   // [b][f][n] fp16, chunk^(f&7) swizzle per 128-n block
__device__ float    g_lp [Bn * Nn * Hh];   // lp * log2e
__device__ __half2  g_FF [Bn * Hh * Nn];   // (2^lc, 2^(0.2lc)) per node
__device__ unsigned g_mxu[Bn * Hh];        // encoded max_j lc'

// ---- PTX helpers ----
static __device__ __forceinline__ uint32_t s2u(const void* p) {
    return (uint32_t)__cvta_generic_to_shared(p);
}
static __device__ __forceinline__ float ex2f(float x) {
    float r; asm("ex2.approx.f32 %0, %1;" : "=f"(r) : "f"(x)); return r;
}
static __device__ __forceinline__ uint32_t prmtb(uint32_t a, uint32_t b, uint32_t sel) {
    uint32_t d; asm("prmt.b32 %0, %1, %2, %3;" : "=r"(d) : "r"(a), "r"(b), "r"(sel)); return d;
}
static __device__ __forceinline__ uint32_t h2b(__half2 v) {
    return *reinterpret_cast<uint32_t*>(&v);
}
static __device__ __forceinline__ __half2 b2h(uint32_t u) {
    return *reinterpret_cast<__half2*>(&u);
}
static __device__ __forceinline__ unsigned encf(float f) {
    int i = __float_as_int(f);
    return (i >= 0) ? ((unsigned)i | 0x80000000u) : ~(unsigned)i;
}
static __device__ __forceinline__ float decf(unsigned u) {
    int i = (u & 0x80000000u) ? (int)(u & 0x7FFFFFFFu) : (int)~u;
    return __int_as_float(i);
}
static __device__ __forceinline__ void mma16816(float& d0, float& d1, float& d2, float& d3,
                                                uint32_t a0, uint32_t a1, uint32_t a2, uint32_t a3,
                                                uint32_t b0, uint32_t b1) {
    asm("mma.sync.aligned.m16n8k16.row.col.f32.f16.f16.f32 "
        "{%0,%1,%2,%3}, {%4,%5,%6,%7}, {%8,%9}, {%0,%1,%2,%3};"
        : "+f"(d0), "+f"(d1), "+f"(d2), "+f"(d3)
        : "r"(a0), "r"(a1), "r"(a2), "r"(a3), "r"(b0), "r"(b1));
}
#define MBAR_INIT(mb, cnt) \
    asm volatile("mbarrier.init.shared.b64 [%0], %1;" :: "r"(mb), "r"(cnt) : "memory")
#define MBAR_EXPECT(mb, bytes) \
    asm volatile("mbarrier.arrive.expect_tx.shared.b64 _, [%0], %1;" :: "r"(mb), "r"(bytes) : "memory")
#define TMA2D(smem, map, x, y, mb) \
    asm volatile("cp.async.bulk.tensor.2d.shared::cta.global.tile.mbarrier::complete_tx::bytes " \
                 "[%0], [%1, {%2, %3}], [%4];" \
                 :: "r"(smem), "l"(map), "r"(x), "r"(y), "r"(mb) : "memory")
static __device__ __forceinline__ void mbar_wait(uint32_t mb, uint32_t parity) {
    asm volatile(
        "{\n\t.reg .pred P;\n\t"
        "WL_%=:\n\t"
        "mbarrier.try_wait.parity.acquire.cta.shared::cta.b64 P, [%0], %1, 0x989680;\n\t"
        "@P bra.uni WD_%=;\n\t"
        "bra.uni WL_%=;\n\t"
        "WD_%=:\n\t}"
        :: "r"(mb), "r"(parity) : "memory");
}

// ---------------------------------------------------------------
// Kernel A: adj fp32 -> fp16 (chunk-swizzled) + fp32 out-tail copy.
// ---------------------------------------------------------------
__global__ __launch_bounds__(256) void k_adj(const float* __restrict__ adj,
                                             float* __restrict__ out_tail,
                                             int copy_adj) {
    if (blockIdx.x == 0 && threadIdx.x < Bn * Hh)
        g_mxu[threadIdx.x] = 0u;
    const size_t i8 = ((size_t)blockIdx.x * 256 + threadIdx.x) * 8;
    const float4 v0 = *(const float4*)(adj + i8);
    const float4 v1 = *(const float4*)(adj + i8 + 4);
    __half hv[8];
    hv[0] = __float2half(v0.x); hv[1] = __float2half(v0.y);
    hv[2] = __float2half(v0.z); hv[3] = __float2half(v0.w);
    hv[4] = __float2half(v1.x); hv[5] = __float2half(v1.y);
    hv[6] = __float2half(v1.z); hv[7] = __float2half(v1.w);

    const size_t r = i8 >> 11;              // global row (incl. batch)
    const int    j = (int)(i8 & (Nn - 1));
    const int    c = (j & 127) >> 3;        // chunk within 128-block
    const size_t base = (r << 11) + (size_t)(j & ~127);
    *(uint4*)(g_adjh + base + ((c ^ ((int)r & 7)) << 3)) = *(const uint4*)hv;

    if (copy_adj) {
        *(float4*)(out_tail + i8)     = v0;
        *(float4*)(out_tail + i8 + 4) = v1;
    }
}

// ---------------------------------------------------------------
// Kernel B: projection + per-node logits, fused. hT written swizzled.
// ---------------------------------------------------------------
__global__ __launch_bounds__(128) void k_proj(const float* __restrict__ nf,
                                              const float* __restrict__ W,
                                              const float* __restrict__ bias,
                                              const float* __restrict__ a) {
    __shared__ float snf[16][132];
    __shared__ float sred[Hh][17];
    const int t  = threadIdx.x;
    const int r0 = blockIdx.x * 16;
#pragma unroll
    for (int r = 0; r < 16; ++r)
        snf[r][t] = nf[(size_t)(r0 + r) * CIN + t];
    __syncthreads();

    float acc[16];
    const float bv = bias[t];
#pragma unroll
    for (int r = 0; r < 16; ++r) acc[r] = bv;

    for (int k4 = 0; k4 < CIN / 4; ++k4) {
        const float w0 = W[(k4 * 4 + 0) * HC + t];
        const float w1 = W[(k4 * 4 + 1) * HC + t];
        const float w2 = W[(k4 * 4 + 2) * HC + t];
        const float w3 = W[(k4 * 4 + 3) * HC + t];
#pragma unroll
        for (int r = 0; r < 16; ++r) {
            const float4 s = *(const float4*)&snf[r][k4 * 4];
            acc[r] = fmaf(s.x, w0, acc[r]);
            acc[r] = fmaf(s.y, w1, acc[r]);
            acc[r] = fmaf(s.z, w2, acc[r]);
            acc[r] = fmaf(s.w, w3, acc[r]);
        }
    }

    const int b  = r0 >> 11;
    const int n0 = r0 & (Nn - 1);

    // hT write: thread t == feature f; 16 consecutive n = 2 swizzled chunks.
    {
        __half hv[16];
#pragma unroll
        for (int r = 0; r < 16; ++r) hv[r] = __float2half(acc[r]);
        const int c = (n0 & 127) >> 3;             // even chunk
        __half* base = g_hT + ((size_t)b * HC + t) * Nn + (n0 & ~127);
        *(uint4*)(base + ((c       ^ (t & 7)) << 3)) = *(const uint4*)&hv[0];
        *(uint4*)(base + (((c + 1) ^ (t & 7)) << 3)) = *(const uint4*)&hv[8];
    }

    __syncthreads();
#pragma unroll
    for (int r = 0; r < 16; ++r)
        snf[r][t] = acc[r];                // snf now holds h
    __syncthreads();

    const int rr = t >> 3;
    const int hb = (t & 7) * 2;
#pragma unroll
    for (int p = 0; p < 2; ++p) {
        const int h = hb + p;
        const float* hv = &snf[rr][h * Cc];
        const float* ap = a + h * 2 * Cc;
        float lp = 0.f, lc = 0.f;
#pragma unroll
        for (int c = 0; c < Cc; ++c) {
            lp = fmaf(hv[c], ap[c],      lp);
            lc = fmaf(hv[c], ap[Cc + c], lc);
        }
        lp *= LOG2E; lc *= LOG2E;
        const int n = r0 + rr;
        g_lp[n * Hh + h] = lp;
        g_FF[((size_t)b * Hh + h) * Nn + (n & (Nn - 1))] =
            __halves2half2(__float2half(ex2f(lc)), __float2half(ex2f(0.2f * lc)));
        sred[h][rr] = lc;
    }
    __syncthreads();
    if (t < Hh) {
        float m = sred[t][0];
#pragma unroll
        for (int r = 1; r < 16; ++r) m = fmaxf(m, sred[t][r]);
        atomicMax(&g_mxu[b * Hh + t], encf(m));
    }
}

// ---------------------------------------------------------------
// Kernel C: fused softmax-attention via mma.m16n8k16.
// Tiles staged via 2 TMA 2D loads per j-block (thread 0) + mbarrier.
// ---------------------------------------------------------------
__global__ __launch_bounds__(512, 2) void k_main(
        const __grid_constant__ CUtensorMap tmh,
        const __grid_constant__ CUtensorMap tma,
        float* __restrict__ out) {
    extern __shared__ __align__(128) __half smem[];
    __shared__ __align__(8) unsigned long long mbar[2];
    __half* const sH[2] = { smem, smem + SH_H };
    __half* const sA[2] = { smem + 2 * SH_H, smem + 2 * SH_H + SH_A };

    const int t    = threadIdx.x;
    const int warp = t >> 5;
    const int lane = t & 31;
    const int gid  = lane >> 2;   // 0..7
    const int tig  = lane & 3;    // 0..3
    const int hh   = warp;

    const int b  = blockIdx.x >> 7;
    const int i0 = (blockIdx.x & 127) * 16;
    const size_t bN = (size_t)b * Nn;

    // ---- mbarrier init ----
    if (t == 0) { MBAR_INIT(s2u(&mbar[0]), 1); MBAR_INIT(s2u(&mbar[1]), 1); }
    asm volatile("fence.proxy.async.shared::cta;" ::: "memory");
    __syncthreads();

    auto issue_tile = [&](int jb, int bufi) {
        const uint32_t mb = s2u(&mbar[bufi]);
        MBAR_EXPECT(mb, TILE_BYTES);
        TMA2D(s2u(sH[bufi]), &tmh, jb * 128, b * HC, mb);
        TMA2D(s2u(sA[bufi]), &tma, jb * 128, (int)(bN + i0), mb);
    };

    // per-row factors E = 2^(lp-m), E' = 2^(0.2lp-m)
    __half2 E0, E0p, E1, E1p;
    {
        const float mx  = decf(g_mxu[b * Hh + hh]);
        const float lp0 = g_lp[(bN + i0 + gid)     * Hh + hh];
        const float lp1 = g_lp[(bN + i0 + gid + 8) * Hh + hh];
        const float s0 = lp0 + mx, s1 = lp1 + mx;
        const float m0 = fmaxf(s0, 0.2f * s0);
        const float m1 = fmaxf(s1, 0.2f * s1);
        E0  = __float2half2_rn(ex2f(lp0 - m0));
        E0p = __float2half2_rn(ex2f(0.2f * lp0 - m0));
        E1  = __float2half2_rn(ex2f(lp1 - m1));
        E1p = __float2half2_rn(ex2f(0.2f * lp1 - m1));
    }

    const __half2* FFb = g_FF + ((size_t)b * Hh + hh) * Nn;

    float dn0 = 0.f, dn1 = 0.f, dn2 = 0.f, dn3 = 0.f;
    float dd0 = 0.f, dd1 = 0.f, dd2 = 0.f, dd3 = 0.f;
    const uint32_t ONES = 0x3C003C00u;

    if (t == 0) issue_tile(0, 0);

    for (int jb = 0; jb < NJB; ++jb) {
        __syncthreads();                       // prior reads of next buffer done
        if (jb + 1 < NJB && t == 0) issue_tile(jb + 1, (jb + 1) & 1);
        mbar_wait(s2u(&mbar[jb & 1]), (jb >> 1) & 1);

        const __half* hbuf = sH[jb & 1];
        const __half* abuf = sA[jb & 1];
        const __half* Hrow  = hbuf + (hh * 8 + gid) * 128 + 2 * tig;
        const __half* arow0 = abuf + gid * 128       + 2 * tig;
        const __half* arow1 = abuf + (gid + 8) * 128 + 2 * tig;

#pragma unroll 2
        for (int ks = 0; ks < 8; ++ks) {
            const int j  = jb * 128 + ks * 16 + 2 * tig;
            const int c0 = ((2 * ks)     ^ gid) << 3;    // swizzled chunk offsets
            const int c1 = ((2 * ks + 1) ^ gid) << 3;

            const uint2 ffl = *(const uint2*)(FFb + j);
            const uint2 ffh = *(const uint2*)(FFb + j + 8);
            const uint32_t F0  = prmtb(ffl.x, ffl.y, 0x5410);
            const uint32_t Fp0 = prmtb(ffl.x, ffl.y, 0x7632);
            const uint32_t F1  = prmtb(ffh.x, ffh.y, 0x5410);
            const uint32_t Fp1 = prmtb(ffh.x, ffh.y, 0x7632);

            const uint32_t bh0 = *(const uint32_t*)(Hrow + c0);
            const uint32_t bh1 = *(const uint32_t*)(Hrow + c1);

            const __half2 m00 = *(const __half2*)(arow0 + c0);
            const __half2 m01 = *(const __half2*)(arow0 + c1);
            const __half2 m10 = *(const __half2*)(arow1 + c0);
            const __half2 m11 = *(const __half2*)(arow1 + c1);

            const __half2 w0lo = __hmax2(__hmul2(b2h(F0),  E0),  __hmul2(b2h(Fp0), E0p));
            const __half2 w1lo = __hmax2(__hmul2(b2h(F0),  E1),  __hmul2(b2h(Fp0), E1p));
            const __half2 w0hi = __hmax2(__hmul2(b2h(F1),  E0),  __hmul2(b2h(Fp1), E0p));
            const __half2 w1hi = __hmax2(__hmul2(b2h(F1),  E1),  __hmul2(b2h(Fp1), E1p));

            const uint32_t ra0 = h2b(__hmul2(w0lo, m00));
            const uint32_t ra1 = h2b(__hmul2(w1lo, m10));
            const uint32_t ra2 = h2b(__hmul2(w0hi, m01));
            const uint32_t ra3 = h2b(__hmul2(w1hi, m11));

            mma16816(dn0, dn1, dn2, dn3, ra0, ra1, ra2, ra3, bh0, bh1);
            mma16816(dd0, dd1, dd2, dd3, ra0, ra1, ra2, ra3, ONES, ONES);
        }
    }

    // ---- epilogue: divide and store ----
    {
        const float inv0 = 1.0f / dd0;
        const float inv1 = 1.0f / dd2;
        float2 o0 = make_float2(dn0 * inv0, dn1 * inv0);
        float2 o1 = make_float2(dn2 * inv1, dn3 * inv1);
        *(float2*)(out + (bN + i0 + gid)     * HC + hh * Cc + 2 * tig) = o0;
        *(float2*)(out + (bN + i0 + gid + 8) * HC + hh * Cc + 2 * tig) = o1;
    }
}

// ---------------------------------------------------------------
extern "C" void kernel_launch(void* const* d_in, const int* in_sizes, int n_in,
                              void* d_out, int out_size) {
    const float* nf   = (const float*)d_in[0];
    const float* adj  = (const float*)d_in[1];
    const float* W    = (const float*)d_in[2];
    const float* bias = (const float*)d_in[3];
    const float* a    = (const float*)d_in[4];
    float* out = (float*)d_out;

    const long long outel = (long long)Bn * Nn * HC;        // 524288
    const long long adjel = (long long)Bn * Nn * Nn;        // 8388608
    const int copy_adj = ((long long)out_size >= outel + adjel) ? 1 : 0;

    // ---- build TMA descriptors (host, via driver entry point) ----
    PFN_tmencode pfn = nullptr;
    cudaDriverEntryPointQueryResult qr;
    cudaGetDriverEntryPoint("cuTensorMapEncodeTiled", (void**)&pfn,
                            cudaEnableDefault, &qr);

    void *p_hT = nullptr, *p_adjh = nullptr;
    cudaGetSymbolAddress(&p_hT, g_hT);
    cudaGetSymbolAddress(&p_adjh, g_adjh);

    CUtensorMap tmh, tma;
    {
        cuuint64_t dims[2]    = { (cuuint64_t)Nn, (cuuint64_t)(Bn * HC) };
        cuuint64_t strides[1] = { (cuuint64_t)Nn * 2 };
        cuuint32_t box[2]     = { 128, 128 };
        cuuint32_t estr[2]    = { 1, 1 };
        pfn(&tmh, CU_TENSOR_MAP_DATA_TYPE_UINT16, 2, p_hT, dims, strides,
            box, estr, CU_TENSOR_MAP_INTERLEAVE_NONE, CU_TENSOR_MAP_SWIZZLE_NONE,
            CU_TENSOR_MAP_L2_PROMOTION_L2_128B, CU_TENSOR_MAP_FLOAT_OOB_FILL_NONE);
    }
    {
        cuuint64_t dims[2]    = { (cuuint64_t)Nn, (cuuint64_t)(Bn * Nn) };
        cuuint64_t strides[1] = { (cuuint64_t)Nn * 2 };
        cuuint32_t box[2]     = { 128, 16 };
        cuuint32_t estr[2]    = { 1, 1 };
        pfn(&tma, CU_TENSOR_MAP_DATA_TYPE_UINT16, 2, p_adjh, dims, strides,
            box, estr, CU_TENSOR_MAP_INTERLEAVE_NONE, CU_TENSOR_MAP_SWIZZLE_NONE,
            CU_TENSOR_MAP_L2_PROMOTION_L2_128B, CU_TENSOR_MAP_FLOAT_OOB_FILL_NONE);
    }

    cudaFuncSetAttribute(k_main, cudaFuncAttributeMaxDynamicSharedMemorySize,
                         SMEM_BYTES);

    k_adj <<<(int)(adjel / 2048), 256>>>(adj, out + outel, copy_adj);
    k_proj<<<Bn * Nn / 16, 128>>>(nf, W, bias, a);
    k_main<<<Bn * (Nn / 16), 512, SMEM_BYTES>>>(tmh, tma, out);
}

// round 10
// speedup vs baseline: 2.1207x; 1.0593x over previous
#include <cuda_runtime.h>
#include <cuda_fp16.h>
#include <cuda.h>
#include <cstdint>

#define Bn   2
#define Nn   2048
#define CIN  128
#define Hh   16
#define Cc   8
#define HC   128
#define LOG2E 1.4426950408889634f
#define NJB  16          // j-blocks of 128

// smem layout (bytes): H 2x32768 | adj fp32 2x8192 | adj fp16 1x4096
#define SO_H0   0
#define SO_H1   32768
#define SO_F0   65536
#define SO_F1   (65536 + 8192)
#define SO_A16  81920
#define SMEM_BYTES (81920 + 4096)
#define TILE_BYTES (32768 + 8192)    // per-buffer expect_tx

// driver-API typedef (not provided by this toolchain's cudaTypedefs.h)
typedef CUresult (*PFN_tmencode)(
    CUtensorMap*, CUtensorMapDataType, cuuint32_t, void*,
    const cuuint64_t*, const cuuint64_t*, const cuuint32_t*, const cuuint32_t*,
    CUtensorMapInterleave, CUtensorMapSwizzle, CUtensorMapL2promotion,
    CUtensorMapFloatOOBfill);

// ---- device scratch ----
__device__ __half   g_hT [Bn * HC * Nn];   // [b][f][n] fp16, chunk^(f&7) swizzle per 128-n block
__device__ float    g_lp [Bn * Nn * Hh];   // lp * log2e
__device__ __half   g_Fa [Bn * Hh * Nn];   // 2^lc, fragment-permuted per 16-group
__device__ __half   g_Fpa[Bn * Hh * Nn];   // 2^(0.2lc), fragment-permuted
__device__ unsigned g_mxu[Bn * Hh];        // encoded max_j lc' (0 == -inf)

// ---- PTX helpers ----
static __device__ __forceinline__ uint32_t s2u(const void* p) {
    return (uint32_t)__cvta_generic_to_shared(p);
}
static __device__ __forceinline__ float ex2f(float x) {
    float r; asm("ex2.approx.f32 %0, %1;" : "=f"(r) : "f"(x)); return r;
}
static __device__ __forceinline__ uint32_t packh2(float lo, float hi) {
    uint32_t d; asm("cvt.rn.f16x2.f32 %0, %1, %2;" : "=r"(d) : "f"(hi), "f"(lo)); return d;
}
static __device__ __forceinline__ uint32_t h2b(__half2 v) {
    return *reinterpret_cast<uint32_t*>(&v);
}
static __device__ __forceinline__ __half2 b2h(uint32_t u) {
    return *reinterpret_cast<__half2*>(&u);
}
static __device__ __forceinline__ unsigned encf(float f) {
    int i = __float_as_int(f);
    return (i >= 0) ? ((unsigned)i | 0x80000000u) : ~(unsigned)i;
}
static __device__ __forceinline__ float decf(unsigned u) {
    int i = (u & 0x80000000u) ? (int)(u & 0x7FFFFFFFu) : (int)~u;
    return __int_as_float(i);
}
static __device__ __forceinline__ void mma16816(float& d0, float& d1, float& d2, float& d3,
                                                uint32_t a0, uint32_t a1, uint32_t a2, uint32_t a3,
                                                uint32_t b0, uint32_t b1) {
    asm("mma.sync.aligned.m16n8k16.row.col.f32.f16.f16.f32 "
        "{%0,%1,%2,%3}, {%4,%5,%6,%7}, {%8,%9}, {%0,%1,%2,%3};"
        : "+f"(d0), "+f"(d1), "+f"(d2), "+f"(d3)
        : "r"(a0), "r"(a1), "r"(a2), "r"(a3), "r"(b0), "r"(b1));
}
#define MBAR_INIT(mb, cnt) \
    asm volatile("mbarrier.init.shared.b64 [%0], %1;" :: "r"(mb), "r"(cnt) : "memory")
#define MBAR_EXPECT(mb, bytes) \
    asm volatile("mbarrier.arrive.expect_tx.shared.b64 _, [%0], %1;" :: "r"(mb), "r"(bytes) : "memory")
#define TMA2D(smem, map, x, y, mb) \
    asm volatile("cp.async.bulk.tensor.2d.shared::cta.global.tile.mbarrier::complete_tx::bytes " \
                 "[%0], [%1, {%2, %3}], [%4];" \
                 :: "r"(smem), "l"(map), "r"(x), "r"(y), "r"(mb) : "memory")
static __device__ __forceinline__ void mbar_wait(uint32_t mb, uint32_t parity) {
    asm volatile(
        "{\n\t.reg .pred P;\n\t"
        "WL_%=:\n\t"
        "mbarrier.try_wait.parity.acquire.cta.shared::cta.b64 P, [%0], %1, 0x989680;\n\t"
        "@P bra.uni WD_%=;\n\t"
        "bra.uni WL_%=;\n\t"
        "WD_%=:\n\t}"
        :: "r"(mb), "r"(parity) : "memory");
}

// ---------------------------------------------------------------
// Kernel B: projection + per-node logits, fused. hT written swizzled;
// F/F' written in MMA-fragment permuted order.
// ---------------------------------------------------------------
__global__ __launch_bounds__(128) void k_proj(const float* __restrict__ nf,
                                              const float* __restrict__ W,
                                              const float* __restrict__ bias,
                                              const float* __restrict__ a) {
    __shared__ float snf[16][132];
    __shared__ float sred[Hh][17];
    const int t  = threadIdx.x;
    const int r0 = blockIdx.x * 16;
#pragma unroll
    for (int r = 0; r < 16; ++r)
        snf[r][t] = nf[(size_t)(r0 + r) * CIN + t];
    __syncthreads();

    float acc[16];
    const float bv = bias[t];
#pragma unroll
    for (int r = 0; r < 16; ++r) acc[r] = bv;

    for (int k4 = 0; k4 < CIN / 4; ++k4) {
        const float w0 = W[(k4 * 4 + 0) * HC + t];
        const float w1 = W[(k4 * 4 + 1) * HC + t];
        const float w2 = W[(k4 * 4 + 2) * HC + t];
        const float w3 = W[(k4 * 4 + 3) * HC + t];
#pragma unroll
        for (int r = 0; r < 16; ++r) {
            const float4 s = *(const float4*)&snf[r][k4 * 4];
            acc[r] = fmaf(s.x, w0, acc[r]);
            acc[r] = fmaf(s.y, w1, acc[r]);
            acc[r] = fmaf(s.z, w2, acc[r]);
            acc[r] = fmaf(s.w, w3, acc[r]);
        }
    }

    const int b  = r0 >> 11;
    const int n0 = r0 & (Nn - 1);

    // hT write: thread t == feature f; 16 consecutive n = 2 swizzled chunks.
    {
        __half hv[16];
#pragma unroll
        for (int r = 0; r < 16; ++r) hv[r] = __float2half(acc[r]);
        const int c = (n0 & 127) >> 3;
        __half* base = g_hT + ((size_t)b * HC + t) * Nn + (n0 & ~127);
        *(uint4*)(base + ((c       ^ (t & 7)) << 3)) = *(const uint4*)&hv[0];
        *(uint4*)(base + (((c + 1) ^ (t & 7)) << 3)) = *(const uint4*)&hv[8];
    }

    __syncthreads();
#pragma unroll
    for (int r = 0; r < 16; ++r)
        snf[r][t] = acc[r];                // snf now holds h
    __syncthreads();

    const int rr = t >> 3;                 // node-in-block 0..15
    const int hb = (t & 7) * 2;
    // fragment slot for position rr within the 16-group
    const int slot = (rr & 1) | (((rr >> 3) & 1) << 1) | (((rr >> 1) & 3) << 2);
#pragma unroll
    for (int p = 0; p < 2; ++p) {
        const int h = hb + p;
        const float* hv = &snf[rr][h * Cc];
        const float* ap = a + h * 2 * Cc;
        float lp = 0.f, lc = 0.f;
#pragma unroll
        for (int c = 0; c < Cc; ++c) {
            lp = fmaf(hv[c], ap[c],      lp);
            lc = fmaf(hv[c], ap[Cc + c], lc);
        }
        lp *= LOG2E; lc *= LOG2E;
        const int n = r0 + rr;
        g_lp[n * Hh + h] = lp;
        const size_t fbase = ((size_t)b * Hh + h) * Nn + n0 + slot;
        g_Fa [fbase] = __float2half(ex2f(lc));
        g_Fpa[fbase] = __float2half(ex2f(0.2f * lc));
        sred[h][rr] = lc;
    }
    __syncthreads();
    if (t < Hh) {
        float m = sred[t][0];
#pragma unroll
        for (int r = 1; r < 16; ++r) m = fmaxf(m, sred[t][r]);
        atomicMax(&g_mxu[b * Hh + t], encf(m));
    }
}

// ---------------------------------------------------------------
// Kernel C: fused softmax-attention via mma.m16n8k16.
// H tile: 1 TMA; adj fp32 tile: 2 TMAs straight from the input.
// In-kernel fp32->fp16 convert (swizzled) + fp32 tail copy, overlapped.
// ---------------------------------------------------------------
__global__ __launch_bounds__(512, 2) void k_main(
        const __grid_constant__ CUtensorMap tmh,
        const __grid_constant__ CUtensorMap tmaf,
        float* __restrict__ out, int copy_adj) {
    extern __shared__ __align__(128) char smem[];
    __shared__ __align__(8) unsigned long long mbar[2];
    __half* const sH[2]  = { (__half*)(smem + SO_H0), (__half*)(smem + SO_H1) };
    float*  const sF[2]  = { (float*)(smem + SO_F0), (float*)(smem + SO_F1) };
    __half* const sA16   = (__half*)(smem + SO_A16);

    const int t    = threadIdx.x;
    const int warp = t >> 5;
    const int lane = t & 31;
    const int gid  = lane >> 2;   // 0..7
    const int tig  = lane & 3;    // 0..3
    const int hh   = warp;

    const int b  = blockIdx.x >> 7;
    const int i0 = (blockIdx.x & 127) * 16;
    const size_t bN = (size_t)b * Nn;

    if (t == 0) { MBAR_INIT(s2u(&mbar[0]), 1); MBAR_INIT(s2u(&mbar[1]), 1); }
    asm volatile("fence.proxy.async.shared::cta;" ::: "memory");
    __syncthreads();

    auto issue_tile = [&](int jb, int bufi) {
        const uint32_t mb = s2u(&mbar[bufi]);
        MBAR_EXPECT(mb, TILE_BYTES);
        TMA2D(s2u(sH[bufi]), &tmh, jb * 128, b * HC, mb);
        TMA2D(s2u(sF[bufi]),        &tmaf, jb * 128,      (int)(bN + i0), mb);
        TMA2D(s2u(sF[bufi]) + 4096, &tmaf, jb * 128 + 64, (int)(bN + i0), mb);
    };

    // per-row factors E = 2^(lp-m), E' = 2^(0.2lp-m)
    __half2 E0, E0p, E1, E1p;
    {
        const float mx  = decf(g_mxu[b * Hh + hh]);
        const float lp0 = g_lp[(bN + i0 + gid)     * Hh + hh];
        const float lp1 = g_lp[(bN + i0 + gid + 8) * Hh + hh];
        const float s0 = lp0 + mx, s1 = lp1 + mx;
        const float m0 = fmaxf(s0, 0.2f * s0);
        const float m1 = fmaxf(s1, 0.2f * s1);
        E0  = __float2half2_rn(ex2f(lp0 - m0));
        E0p = __float2half2_rn(ex2f(0.2f * lp0 - m0));
        E1  = __float2half2_rn(ex2f(lp1 - m1));
        E1p = __float2half2_rn(ex2f(0.2f * lp1 - m1));
    }

    const __half* Fab  = g_Fa  + ((size_t)b * Hh + hh) * Nn;
    const __half* Fpb  = g_Fpa + ((size_t)b * Hh + hh) * Nn;

    float dn0 = 0.f, dn1 = 0.f, dn2 = 0.f, dn3 = 0.f;
    float dd0 = 0.f, dd1 = 0.f, dd2 = 0.f, dd3 = 0.f;
    const uint32_t ONES = 0x3C003C00u;

    // convert-step indices (thread t handles row=warp, cols 4*lane..+3)
    const int cv_panel = lane >> 4;
    const int cv_off   = (lane & 15) * 4;             // float offset in panel row
    const int cv_chunk = lane >> 1;                   // 8-half chunk 0..15
    float* cv_tail = copy_adj
        ? out + (size_t)Bn * Nn * HC + (bN + i0 + warp) * (size_t)Nn + lane * 4
        : nullptr;
    __half* cv_dst = sA16 + warp * 128 + ((cv_chunk ^ (warp & 7)) << 3) + (lane & 1) * 4;

    if (t == 0) issue_tile(0, 0);

    for (int jb = 0; jb < NJB; ++jb) {
        __syncthreads();                   // all warps done with prior compute + sA16
        if (jb + 1 < NJB && t == 0) issue_tile(jb + 1, (jb + 1) & 1);
        mbar_wait(s2u(&mbar[jb & 1]), (jb >> 1) & 1);

        // ---- convert fp32 adj tile -> swizzled fp16, and tail copy ----
        {
            const float4 v = *(const float4*)(sF[jb & 1] + cv_panel * 1024 + warp * 64 + cv_off);
            uint2 hp;
            hp.x = packh2(v.x, v.y);
            hp.y = packh2(v.z, v.w);
            *(uint2*)cv_dst = hp;
            if (copy_adj) *(float4*)(cv_tail + jb * 128) = v;
        }
        __syncthreads();

        const __half* hbuf = sH[jb & 1];
        const __half* Hrow  = hbuf + (hh * 8 + gid) * 128 + 2 * tig;
        const __half* arow0 = sA16 + gid * 128       + 2 * tig;
        const __half* arow1 = sA16 + (gid + 8) * 128 + 2 * tig;
        const __half* Faj  = Fab + jb * 128 + 4 * tig;
        const __half* Fpj  = Fpb + jb * 128 + 4 * tig;

#pragma unroll
        for (int ks = 0; ks < 8; ++ks) {
            const int c0 = ((2 * ks)     ^ gid) << 3;
            const int c1 = ((2 * ks + 1) ^ gid) << 3;

            const uint2 fa  = *(const uint2*)(Faj + ks * 16);
            const uint2 fpa = *(const uint2*)(Fpj + ks * 16);

            const uint32_t bh0 = *(const uint32_t*)(Hrow + c0);
            const uint32_t bh1 = *(const uint32_t*)(Hrow + c1);

            const __half2 m00 = *(const __half2*)(arow0 + c0);
            const __half2 m01 = *(const __half2*)(arow0 + c1);
            const __half2 m10 = *(const __half2*)(arow1 + c0);
            const __half2 m11 = *(const __half2*)(arow1 + c1);

            const __half2 w0lo = __hmax2(__hmul2(b2h(fa.x),  E0),  __hmul2(b2h(fpa.x), E0p));
            const __half2 w1lo = __hmax2(__hmul2(b2h(fa.x),  E1),  __hmul2(b2h(fpa.x), E1p));
            const __half2 w0hi = __hmax2(__hmul2(b2h(fa.y),  E0),  __hmul2(b2h(fpa.y), E0p));
            const __half2 w1hi = __hmax2(__hmul2(b2h(fa.y),  E1),  __hmul2(b2h(fpa.y), E1p));

            const uint32_t ra0 = h2b(__hmul2(w0lo, m00));
            const uint32_t ra1 = h2b(__hmul2(w1lo, m10));
            const uint32_t ra2 = h2b(__hmul2(w0hi, m01));
            const uint32_t ra3 = h2b(__hmul2(w1hi, m11));

            mma16816(dn0, dn1, dn2, dn3, ra0, ra1, ra2, ra3, bh0, bh1);
            mma16816(dd0, dd1, dd2, dd3, ra0, ra1, ra2, ra3, ONES, ONES);
        }
    }

    // ---- epilogue: divide and store ----
    {
        const float inv0 = 1.0f / dd0;
        const float inv1 = 1.0f / dd2;
        float2 o0 = make_float2(dn0 * inv0, dn1 * inv0);
        float2 o1 = make_float2(dn2 * inv1, dn3 * inv1);
        *(float2*)(out + (bN + i0 + gid)     * HC + hh * Cc + 2 * tig) = o0;
        *(float2*)(out + (bN + i0 + gid + 8) * HC + hh * Cc + 2 * tig) = o1;
    }
}

// ---------------------------------------------------------------
extern "C" void kernel_launch(void* const* d_in, const int* in_sizes, int n_in,
                              void* d_out, int out_size) {
    const float* nf   = (const float*)d_in[0];
    const float* adj  = (const float*)d_in[1];
    const float* W    = (const float*)d_in[2];
    const float* bias = (const float*)d_in[3];
    const float* a    = (const float*)d_in[4];
    float* out = (float*)d_out;

    const long long outel = (long long)Bn * Nn * HC;        // 524288
    const long long adjel = (long long)Bn * Nn * Nn;        // 8388608
    const int copy_adj = ((long long)out_size >= outel + adjel) ? 1 : 0;

    // ---- TMA descriptors ----
    PFN_tmencode pfn = nullptr;
    cudaDriverEntryPointQueryResult qr;
    cudaGetDriverEntryPoint("cuTensorMapEncodeTiled", (void**)&pfn,
                            cudaEnableDefault, &qr);

    void *p_hT = nullptr, *p_mxu = nullptr;
    cudaGetSymbolAddress(&p_hT, g_hT);
    cudaGetSymbolAddress(&p_mxu, g_mxu);

    CUtensorMap tmh, tmaf;
    {
        cuuint64_t dims[2]    = { (cuuint64_t)Nn, (cuuint64_t)(Bn * HC) };
        cuuint64_t strides[1] = { (cuuint64_t)Nn * 2 };
        cuuint32_t box[2]     = { 128, 128 };
        cuuint32_t estr[2]    = { 1, 1 };
        pfn(&tmh, CU_TENSOR_MAP_DATA_TYPE_UINT16, 2, p_hT, dims, strides,
            box, estr, CU_TENSOR_MAP_INTERLEAVE_NONE, CU_TENSOR_MAP_SWIZZLE_NONE,
            CU_TENSOR_MAP_L2_PROMOTION_L2_128B, CU_TENSOR_MAP_FLOAT_OOB_FILL_NONE);
    }
    {
        cuuint64_t dims[2]    = { (cuuint64_t)Nn, (cuuint64_t)(Bn * Nn) };
        cuuint64_t strides[1] = { (cuuint64_t)Nn * 4 };
        cuuint32_t box[2]     = { 64, 16 };
        cuuint32_t estr[2]    = { 1, 1 };
        pfn(&tmaf, CU_TENSOR_MAP_DATA_TYPE_FLOAT32, 2, (void*)adj, dims, strides,
            box, estr, CU_TENSOR_MAP_INTERLEAVE_NONE, CU_TENSOR_MAP_SWIZZLE_NONE,
            CU_TENSOR_MAP_L2_PROMOTION_L2_128B, CU_TENSOR_MAP_FLOAT_OOB_FILL_NONE);
    }

    cudaFuncSetAttribute(k_main, cudaFuncAttributeMaxDynamicSharedMemorySize,
                         SMEM_BYTES);

    cudaMemsetAsync(p_mxu, 0, Bn * Hh * sizeof(unsigned));
    k_proj<<<Bn * Nn / 16, 128>>>(nf, W, bias, a);
    k_main<<<Bn * (Nn / 16), 512, SMEM_BYTES>>>(tmh, tmaf, out, copy_adj);
}

// round 12
// speedup vs baseline: 2.1602x; 1.0186x over previous
#include <cuda_runtime.h>
#include <cuda_fp16.h>
#include <cuda.h>
#include <cstdint>

#define Bn   2
#define Nn   2048
#define CIN  128
#define Hh   16
#define Cc   8
#define HC   128
#define LOG2E 1.4426950408889634f
#define NJB  16          // j-blocks of 128

// smem layout (bytes): H 2x32768 | adj fp32 2x8192 | adj fp16 2x4096
#define SO_H0   0
#define SO_H1   32768
#define SO_F0   65536
#define SO_F1   (65536 + 8192)
#define SO_A0   81920
#define SO_A1   (81920 + 4096)
#define SMEM_BYTES (81920 + 8192)
#define TILE_BYTES (32768 + 8192)    // per-buffer expect_tx

// driver-API typedef (not provided by this toolchain's cudaTypedefs.h)
typedef CUresult (*PFN_tmencode)(
    CUtensorMap*, CUtensorMapDataType, cuuint32_t, void*,
    const cuuint64_t*, const cuuint64_t*, const cuuint32_t*, const cuuint32_t*,
    CUtensorMapInterleave, CUtensorMapSwizzle, CUtensorMapL2promotion,
    CUtensorMapFloatOOBfill);

// ---- device scratch ----
// g_hT2: per (b, j-block): [chunk 0..15][f 0..127][8 halves]  (32KB contiguous)
__device__ __half   g_hT2[Bn * HC * Nn];
__device__ float    g_lp [Bn * Nn * Hh];   // lp * log2e
__device__ __half   g_Fa [Bn * Hh * Nn];   // 2^lc, fragment-permuted per 16-group
__device__ __half   g_Fpa[Bn * Hh * Nn];   // 2^(0.2lc), fragment-permuted
__device__ unsigned g_mxu[Bn * Hh];        // encoded max_j lc' (0 == -inf)

// ---- PTX helpers ----
static __device__ __forceinline__ uint32_t s2u(const void* p) {
    return (uint32_t)__cvta_generic_to_shared(p);
}
static __device__ __forceinline__ float ex2f(float x) {
    float r; asm("ex2.approx.f32 %0, %1;" : "=f"(r) : "f"(x)); return r;
}
static __device__ __forceinline__ uint32_t packh2(float lo, float hi) {
    uint32_t d; asm("cvt.rn.f16x2.f32 %0, %1, %2;" : "=r"(d) : "f"(hi), "f"(lo)); return d;
}
static __device__ __forceinline__ uint32_t h2b(__half2 v) {
    return *reinterpret_cast<uint32_t*>(&v);
}
static __device__ __forceinline__ __half2 b2h(uint32_t u) {
    return *reinterpret_cast<__half2*>(&u);
}
static __device__ __forceinline__ unsigned encf(float f) {
    int i = __float_as_int(f);
    return (i >= 0) ? ((unsigned)i | 0x80000000u) : ~(unsigned)i;
}
static __device__ __forceinline__ float decf(unsigned u) {
    int i = (u & 0x80000000u) ? (int)(u & 0x7FFFFFFFu) : (int)~u;
    return __int_as_float(i);
}
static __device__ __forceinline__ void mma16816(float& d0, float& d1, float& d2, float& d3,
                                                uint32_t a0, uint32_t a1, uint32_t a2, uint32_t a3,
                                                uint32_t b0, uint32_t b1) {
    asm("mma.sync.aligned.m16n8k16.row.col.f32.f16.f16.f32 "
        "{%0,%1,%2,%3}, {%4,%5,%6,%7}, {%8,%9}, {%0,%1,%2,%3};"
        : "+f"(d0), "+f"(d1), "+f"(d2), "+f"(d3)
        : "r"(a0), "r"(a1), "r"(a2), "r"(a3), "r"(b0), "r"(b1));
}
#define MBAR_INIT(mb, cnt) \
    asm volatile("mbarrier.init.shared.b64 [%0], %1;" :: "r"(mb), "r"(cnt) : "memory")
#define MBAR_EXPECT(mb, bytes) \
    asm volatile("mbarrier.arrive.expect_tx.shared.b64 _, [%0], %1;" :: "r"(mb), "r"(bytes) : "memory")
#define TMA2D(smem, map, x, y, mb) \
    asm volatile("cp.async.bulk.tensor.2d.shared::cta.global.tile.mbarrier::complete_tx::bytes " \
                 "[%0], [%1, {%2, %3}], [%4];" \
                 :: "r"(smem), "l"(map), "r"(x), "r"(y), "r"(mb) : "memory")
static __device__ __forceinline__ void mbar_wait(uint32_t mb, uint32_t parity) {
    asm volatile(
        "{\n\t.reg .pred P;\n\t"
        "WL_%=:\n\t"
        "mbarrier.try_wait.parity.acquire.cta.shared::cta.b64 P, [%0], %1, 0x989680;\n\t"
        "@P bra.uni WD_%=;\n\t"
        "bra.uni WL_%=;\n\t"
        "WD_%=:\n\t}"
        :: "r"(mb), "r"(parity) : "memory");
}

// ---------------------------------------------------------------
// Kernel B: projection + per-node logits, fused.
// hT2 written chunk-major; F/F' fragment-permuted.
// ---------------------------------------------------------------
__global__ __launch_bounds__(128) void k_proj(const float* __restrict__ nf,
                                              const float* __restrict__ W,
                                              const float* __restrict__ bias,
                                              const float* __restrict__ a) {
    __shared__ float snf[16][132];
    __shared__ float sred[Hh][17];
    const int t  = threadIdx.x;
    const int r0 = blockIdx.x * 16;
#pragma unroll
    for (int r = 0; r < 16; ++r)
        snf[r][t] = nf[(size_t)(r0 + r) * CIN + t];
    __syncthreads();

    float acc[16];
    const float bv = bias[t];
#pragma unroll
    for (int r = 0; r < 16; ++r) acc[r] = bv;

    for (int k4 = 0; k4 < CIN / 4; ++k4) {
        const float w0 = W[(k4 * 4 + 0) * HC + t];
        const float w1 = W[(k4 * 4 + 1) * HC + t];
        const float w2 = W[(k4 * 4 + 2) * HC + t];
        const float w3 = W[(k4 * 4 + 3) * HC + t];
#pragma unroll
        for (int r = 0; r < 16; ++r) {
            const float4 s = *(const float4*)&snf[r][k4 * 4];
            acc[r] = fmaf(s.x, w0, acc[r]);
            acc[r] = fmaf(s.y, w1, acc[r]);
            acc[r] = fmaf(s.z, w2, acc[r]);
            acc[r] = fmaf(s.w, w3, acc[r]);
        }
    }

    const int b  = r0 >> 11;
    const int n0 = r0 & (Nn - 1);

    // hT2 write (chunk-major): thread t == feature f; 16 n = chunks c, c+1.
    {
        __half hv[16];
#pragma unroll
        for (int r = 0; r < 16; ++r) hv[r] = __float2half(acc[r]);
        const int jb = n0 >> 7;
        const int c  = (n0 & 127) >> 3;
        __half* base = g_hT2 + ((((size_t)b * NJB + jb) * 16 + c) * 128 + t) * 8;
        *(uint4*)base          = *(const uint4*)&hv[0];
        *(uint4*)(base + 1024) = *(const uint4*)&hv[8];   // chunk c+1
    }

    __syncthreads();
#pragma unroll
    for (int r = 0; r < 16; ++r)
        snf[r][t] = acc[r];                // snf now holds h
    __syncthreads();

    const int rr = t >> 3;                 // node-in-block 0..15
    const int hb = (t & 7) * 2;
    const int slot = (rr & 1) | (((rr >> 3) & 1) << 1) | (((rr >> 1) & 3) << 2);
#pragma unroll
    for (int p = 0; p < 2; ++p) {
        const int h = hb + p;
        const float* hv = &snf[rr][h * Cc];
        const float* ap = a + h * 2 * Cc;
        float lp = 0.f, lc = 0.f;
#pragma unroll
        for (int c = 0; c < Cc; ++c) {
            lp = fmaf(hv[c], ap[c],      lp);
            lc = fmaf(hv[c], ap[Cc + c], lc);
        }
        lp *= LOG2E; lc *= LOG2E;
        const int n = r0 + rr;
        g_lp[n * Hh + h] = lp;
        const size_t fbase = ((size_t)b * Hh + h) * Nn + n0 + slot;
        g_Fa [fbase] = __float2half(ex2f(lc));
        g_Fpa[fbase] = __float2half(ex2f(0.2f * lc));
        sred[h][rr] = lc;
    }
    __syncthreads();
    if (t < Hh) {
        float m = sred[t][0];
#pragma unroll
        for (int r = 1; r < 16; ++r) m = fmaxf(m, sred[t][r]);
        atomicMax(&g_mxu[b * Hh + t], encf(m));
    }
}

// ---------------------------------------------------------------
// Kernel C: fused softmax-attention via mma.m16n8k16.
// Chunk-major smem layouts -> all inner LDS offsets immediate,
// bank-conflict-free without swizzle ALU. One barrier per j-block.
// ---------------------------------------------------------------
__global__ __launch_bounds__(512, 2) void k_main(
        const __grid_constant__ CUtensorMap tmh,
        const __grid_constant__ CUtensorMap tmaf,
        float* __restrict__ out, int copy_adj) {
    extern __shared__ __align__(128) char smem[];
    __shared__ __align__(8) unsigned long long mbar[2];
    __half* const sH[2] = { (__half*)(smem + SO_H0), (__half*)(smem + SO_H1) };
    float*  const sF[2] = { (float*)(smem + SO_F0), (float*)(smem + SO_F1) };
    __half* const sA[2] = { (__half*)(smem + SO_A0), (__half*)(smem + SO_A1) };

    const int t    = threadIdx.x;
    const int warp = t >> 5;
    const int lane = t & 31;
    const int gid  = lane >> 2;   // 0..7
    const int tig  = lane & 3;    // 0..3
    const int hh   = warp;

    const int b  = blockIdx.x >> 7;
    const int i0 = (blockIdx.x & 127) * 16;
    const size_t bN = (size_t)b * Nn;

    if (t == 0) { MBAR_INIT(s2u(&mbar[0]), 1); MBAR_INIT(s2u(&mbar[1]), 1); }
    asm volatile("fence.proxy.async.shared::cta;" ::: "memory");
    __syncthreads();

    auto issue_tile = [&](int jb, int bufi) {
        const uint32_t mb = s2u(&mbar[bufi]);
        MBAR_EXPECT(mb, TILE_BYTES);
        TMA2D(s2u(sH[bufi]), &tmh, 0, (b * NJB + jb) * 128, mb);
        TMA2D(s2u(sF[bufi]),        &tmaf, jb * 128,      (int)(bN + i0), mb);
        TMA2D(s2u(sF[bufi]) + 4096, &tmaf, jb * 128 + 64, (int)(bN + i0), mb);
    };

    // per-row factors E = 2^(lp-m), E' = 2^(0.2lp-m)
    __half2 E0, E0p, E1, E1p;
    {
        const float mx  = decf(g_mxu[b * Hh + hh]);
        const float lp0 = g_lp[(bN + i0 + gid)     * Hh + hh];
        const float lp1 = g_lp[(bN + i0 + gid + 8) * Hh + hh];
        const float s0 = lp0 + mx, s1 = lp1 + mx;
        const float m0 = fmaxf(s0, 0.2f * s0);
        const float m1 = fmaxf(s1, 0.2f * s1);
        E0  = __float2half2_rn(ex2f(lp0 - m0));
        E0p = __float2half2_rn(ex2f(0.2f * lp0 - m0));
        E1  = __float2half2_rn(ex2f(lp1 - m1));
        E1p = __float2half2_rn(ex2f(0.2f * lp1 - m1));
    }

    const __half* Fab = g_Fa  + ((size_t)b * Hh + hh) * Nn + 4 * tig;
    const __half* Fpb = g_Fpa + ((size_t)b * Hh + hh) * Nn + 4 * tig;

    float dn0 = 0.f, dn1 = 0.f, dn2 = 0.f, dn3 = 0.f;
    float dd0 = 0.f, dd1 = 0.f, dd2 = 0.f, dd3 = 0.f;
    const uint32_t ONES = 0x3C003C00u;

    // convert-step mapping: thread t handles floats [4t, 4t+4)
    const int cv_row = (t >> 4) & 15;
    const int cv_c   = (t >> 8) * 8 + ((t & 15) >> 1);   // dest chunk
    const int cv_w   = (t & 1) * 4;                      // within-chunk half
    float* cv_tail = copy_adj
        ? out + (size_t)Bn * Nn * HC + (bN + i0 + cv_row) * (size_t)Nn
              + (t >> 8) * 64 + (t & 15) * 4
        : nullptr;

    if (t == 0) issue_tile(0, 0);

    for (int jb = 0; jb < NJB; ++jb) {
        const int bi = jb & 1;
        mbar_wait(s2u(&mbar[bi]), (jb >> 1) & 1);

        // ---- convert fp32 adj tile -> chunk-major fp16, + tail copy ----
        {
            const float4 v = *(const float4*)(sF[bi] + 4 * t);
            uint2 hp;
            hp.x = packh2(v.x, v.y);
            hp.y = packh2(v.z, v.w);
            *(uint2*)(sA[bi] + (cv_c * 16 + cv_row) * 8 + cv_w) = hp;
            if (copy_adj) *(float4*)(cv_tail + jb * 128) = v;
        }
        __syncthreads();
        if (jb + 1 < NJB && t == 0) issue_tile(jb + 1, (jb + 1) & 1);

        // per-thread bases (all inner offsets immediate)
        const char* Hp  = (const char*)sH[bi] + (hh * 8 + gid) * 16 + tig * 4;
        const char* Ap0 = (const char*)sA[bi] + gid * 16       + tig * 4;
        const char* Ap1 = (const char*)sA[bi] + (gid + 8) * 16 + tig * 4;
        const __half* Faj = Fab + jb * 128;
        const __half* Fpj = Fpb + jb * 128;

#pragma unroll
        for (int ks = 0; ks < 8; ++ks) {
            const uint2 fa  = *(const uint2*)(Faj + ks * 16);
            const uint2 fpa = *(const uint2*)(Fpj + ks * 16);

            const uint32_t bh0 = *(const uint32_t*)(Hp + (2 * ks)     * 2048);
            const uint32_t bh1 = *(const uint32_t*)(Hp + (2 * ks + 1) * 2048);

            const __half2 m00 = *(const __half2*)(Ap0 + (2 * ks)     * 256);
            const __half2 m01 = *(const __half2*)(Ap0 + (2 * ks + 1) * 256);
            const __half2 m10 = *(const __half2*)(Ap1 + (2 * ks)     * 256);
            const __half2 m11 = *(const __half2*)(Ap1 + (2 * ks + 1) * 256);

            const __half2 w0lo = __hmax2(__hmul2(b2h(fa.x),  E0),  __hmul2(b2h(fpa.x), E0p));
            const __half2 w1lo = __hmax2(__hmul2(b2h(fa.x),  E1),  __hmul2(b2h(fpa.x), E1p));
            const __half2 w0hi = __hmax2(__hmul2(b2h(fa.y),  E0),  __hmul2(b2h(fpa.y), E0p));
            const __half2 w1hi = __hmax2(__hmul2(b2h(fa.y),  E1),  __hmul2(b2h(fpa.y), E1p));

            const uint32_t ra0 = h2b(__hmul2(w0lo, m00));
            const uint32_t ra1 = h2b(__hmul2(w1lo, m10));
            const uint32_t ra2 = h2b(__hmul2(w0hi, m01));
            const uint32_t ra3 = h2b(__hmul2(w1hi, m11));

            mma16816(dn0, dn1, dn2, dn3, ra0, ra1, ra2, ra3, bh0, bh1);
            mma16816(dd0, dd1, dd2, dd3, ra0, ra1, ra2, ra3, ONES, ONES);
        }
    }

    // ---- epilogue: divide and store ----
    {
        const float inv0 = 1.0f / dd0;
        const float inv1 = 1.0f / dd2;
        float2 o0 = make_float2(dn0 * inv0, dn1 * inv0);
        float2 o1 = make_float2(dn2 * inv1, dn3 * inv1);
        *(float2*)(out + (bN + i0 + gid)     * HC + hh * Cc + 2 * tig) = o0;
        *(float2*)(out + (bN + i0 + gid + 8) * HC + hh * Cc + 2 * tig) = o1;
    }
}

// ---------------------------------------------------------------
extern "C" void kernel_launch(void* const* d_in, const int* in_sizes, int n_in,
                              void* d_out, int out_size) {
    const float* nf   = (const float*)d_in[0];
    const float* adj  = (const float*)d_in[1];
    const float* W    = (const float*)d_in[2];
    const float* bias = (const float*)d_in[3];
    const float* a    = (const float*)d_in[4];
    float* out = (float*)d_out;

    const long long outel = (long long)Bn * Nn * HC;        // 524288
    const long long adjel = (long long)Bn * Nn * Nn;        // 8388608
    const int copy_adj = ((long long)out_size >= outel + adjel) ? 1 : 0;

    // ---- TMA descriptors ----
    PFN_tmencode pfn = nullptr;
    cudaDriverEntryPointQueryResult qr;
    cudaGetDriverEntryPoint("cuTensorMapEncodeTiled", (void**)&pfn,
                            cudaEnableDefault, &qr);

    void *p_hT = nullptr, *p_mxu = nullptr;
    cudaGetSymbolAddress(&p_hT, g_hT2);
    cudaGetSymbolAddress(&p_mxu, g_mxu);

    CUtensorMap tmh, tmaf;
    {
        // g_hT2 as 2D: 128 halves wide (256B rows), Bn*NJB*128 rows total.
        // One 32KB tile == 128 consecutive rows.
        cuuint64_t dims[2]    = { 128, (cuuint64_t)(Bn * NJB * 128) };
        cuuint64_t strides[1] = { 256 };
        cuuint32_t box[2]     = { 128, 128 };
        cuuint32_t estr[2]    = { 1, 1 };
        pfn(&tmh, CU_TENSOR_MAP_DATA_TYPE_UINT16, 2, p_hT, dims, strides,
            box, estr, CU_TENSOR_MAP_INTERLEAVE_NONE, CU_TENSOR_MAP_SWIZZLE_NONE,
            CU_TENSOR_MAP_L2_PROMOTION_L2_128B, CU_TENSOR_MAP_FLOAT_OOB_FILL_NONE);
    }
    {
        cuuint64_t dims[2]    = { (cuuint64_t)Nn, (cuuint64_t)(Bn * Nn) };
        cuuint64_t strides[1] = { (cuuint64_t)Nn * 4 };
        cuuint32_t box[2]     = { 64, 16 };
        cuuint32_t estr[2]    = { 1, 1 };
        pfn(&tmaf, CU_TENSOR_MAP_DATA_TYPE_FLOAT32, 2, (void*)adj, dims, strides,
            box, estr, CU_TENSOR_MAP_INTERLEAVE_NONE, CU_TENSOR_MAP_SWIZZLE_NONE,
            CU_TENSOR_MAP_L2_PROMOTION_L2_128B, CU_TENSOR_MAP_FLOAT_OOB_FILL_NONE);
    }

    cudaFuncSetAttribute(k_main, cudaFuncAttributeMaxDynamicSharedMemorySize,
                         SMEM_BYTES);

    cudaMemsetAsync(p_mxu, 0, Bn * Hh * sizeof(unsigned));
    k_proj<<<Bn * Nn / 16, 128>>>(nf, W, bias, a);
    k_main<<<Bn * (Nn / 16), 512, SMEM_BYTES>>>(tmh, tmaf, out, copy_adj);
}

// round 13
// speedup vs baseline: 2.4144x; 1.1177x over previous
#include <cuda_runtime.h>
#include <cuda_fp16.h>
#include <cuda.h>
#include <cstdint>

#define Bn   2
#define Nn   2048
#define CIN  128
#define Hh   16
#define Cc   8
#define HC   128
#define LOG2E 1.4426950408889634f
#define NJB  16          // j-blocks of 128

// smem (bytes): adj fp32 ring 4x8192 | adj fp16 2x4352 (chunk stride 272)
#define SO_F    0
#define SF_STRIDE 8192
#define SO_A    (4 * 8192)
#define SA_STRIDE 4352
#define SA_CH   272              // bytes per chunk (16 rows x 16B + 16B pad)
#define SMEM_BYTES (4 * 8192 + 2 * 4352)
#define TILE_BYTES 8192          // per-stage expect_tx (adj fp32 only)

// driver-API typedef (not provided by this toolchain's cudaTypedefs.h)
typedef CUresult (*PFN_tmencode)(
    CUtensorMap*, CUtensorMapDataType, cuuint32_t, void*,
    const cuuint64_t*, const cuuint64_t*, const cuuint32_t*, const cuuint32_t*,
    CUtensorMapInterleave, CUtensorMapSwizzle, CUtensorMapL2promotion,
    CUtensorMapFloatOOBfill);

// ---- device scratch ----
// g_hT2: per (b, j-block): [chunk 0..15][f 0..127][8 halves]  (32KB contiguous)
__device__ __half   g_hT2[Bn * HC * Nn];
__device__ float    g_lp [Bn * Nn * Hh];   // lp * log2e
__device__ __half   g_Fa [Bn * Hh * Nn];   // 2^lc, fragment-permuted per 16-group
__device__ __half   g_Fpa[Bn * Hh * Nn];   // 2^(0.2lc), fragment-permuted
__device__ unsigned g_mxu[Bn * Hh];        // encoded max_j lc' (0 == -inf)

// ---- PTX helpers ----
static __device__ __forceinline__ uint32_t s2u(const void* p) {
    return (uint32_t)__cvta_generic_to_shared(p);
}
static __device__ __forceinline__ float ex2f(float x) {
    float r; asm("ex2.approx.f32 %0, %1;" : "=f"(r) : "f"(x)); return r;
}
static __device__ __forceinline__ uint32_t packh2(float lo, float hi) {
    uint32_t d; asm("cvt.rn.f16x2.f32 %0, %1, %2;" : "=r"(d) : "f"(hi), "f"(lo)); return d;
}
static __device__ __forceinline__ uint32_t h2b(__half2 v) {
    return *reinterpret_cast<uint32_t*>(&v);
}
static __device__ __forceinline__ __half2 b2h(uint32_t u) {
    return *reinterpret_cast<__half2*>(&u);
}
static __device__ __forceinline__ unsigned encf(float f) {
    int i = __float_as_int(f);
    return (i >= 0) ? ((unsigned)i | 0x80000000u) : ~(unsigned)i;
}
static __device__ __forceinline__ float decf(unsigned u) {
    int i = (u & 0x80000000u) ? (int)(u & 0x7FFFFFFFu) : (int)~u;
    return __int_as_float(i);
}
static __device__ __forceinline__ void mma16816(float& d0, float& d1, float& d2, float& d3,
                                                uint32_t a0, uint32_t a1, uint32_t a2, uint32_t a3,
                                                uint32_t b0, uint32_t b1) {
    asm("mma.sync.aligned.m16n8k16.row.col.f32.f16.f16.f32 "
        "{%0,%1,%2,%3}, {%4,%5,%6,%7}, {%8,%9}, {%0,%1,%2,%3};"
        : "+f"(d0), "+f"(d1), "+f"(d2), "+f"(d3)
        : "r"(a0), "r"(a1), "r"(a2), "r"(a3), "r"(b0), "r"(b1));
}
#define MBAR_INIT(mb, cnt) \
    asm volatile("mbarrier.init.shared.b64 [%0], %1;" :: "r"(mb), "r"(cnt) : "memory")
#define MBAR_EXPECT(mb, bytes) \
    asm volatile("mbarrier.arrive.expect_tx.shared.b64 _, [%0], %1;" :: "r"(mb), "r"(bytes) : "memory")
#define TMA2D(smem, map, x, y, mb) \
    asm volatile("cp.async.bulk.tensor.2d.shared::cta.global.tile.mbarrier::complete_tx::bytes " \
                 "[%0], [%1, {%2, %3}], [%4];" \
                 :: "r"(smem), "l"(map), "r"(x), "r"(y), "r"(mb) : "memory")
static __device__ __forceinline__ void mbar_wait(uint32_t mb, uint32_t parity) {
    asm volatile(
        "{\n\t.reg .pred P;\n\t"
        "WL_%=:\n\t"
        "mbarrier.try_wait.parity.acquire.cta.shared::cta.b64 P, [%0], %1, 0x989680;\n\t"
        "@P bra.uni WD_%=;\n\t"
        "bra.uni WL_%=;\n\t"
        "WD_%=:\n\t}"
        :: "r"(mb), "r"(parity) : "memory");
}

// ---------------------------------------------------------------
// Kernel B: projection + per-node logits, fused.
// hT2 written chunk-major; F/F' fragment-permuted.
// ---------------------------------------------------------------
__global__ __launch_bounds__(128) void k_proj(const float* __restrict__ nf,
                                              const float* __restrict__ W,
                                              const float* __restrict__ bias,
                                              const float* __restrict__ a) {
    __shared__ float snf[16][132];
    __shared__ float sred[Hh][17];
    const int t  = threadIdx.x;
    const int r0 = blockIdx.x * 16;
#pragma unroll
    for (int r = 0; r < 16; ++r)
        snf[r][t] = nf[(size_t)(r0 + r) * CIN + t];
    __syncthreads();

    float acc[16];
    const float bv = bias[t];
#pragma unroll
    for (int r = 0; r < 16; ++r) acc[r] = bv;

    for (int k4 = 0; k4 < CIN / 4; ++k4) {
        const float w0 = W[(k4 * 4 + 0) * HC + t];
        const float w1 = W[(k4 * 4 + 1) * HC + t];
        const float w2 = W[(k4 * 4 + 2) * HC + t];
        const float w3 = W[(k4 * 4 + 3) * HC + t];
#pragma unroll
        for (int r = 0; r < 16; ++r) {
            const float4 s = *(const float4*)&snf[r][k4 * 4];
            acc[r] = fmaf(s.x, w0, acc[r]);
            acc[r] = fmaf(s.y, w1, acc[r]);
            acc[r] = fmaf(s.z, w2, acc[r]);
            acc[r] = fmaf(s.w, w3, acc[r]);
        }
    }

    const int b  = r0 >> 11;
    const int n0 = r0 & (Nn - 1);

    // hT2 write (chunk-major): thread t == feature f; 16 n = chunks c, c+1.
    {
        __half hv[16];
#pragma unroll
        for (int r = 0; r < 16; ++r) hv[r] = __float2half(acc[r]);
        const int jb = n0 >> 7;
        const int c  = (n0 & 127) >> 3;
        __half* base = g_hT2 + ((((size_t)b * NJB + jb) * 16 + c) * 128 + t) * 8;
        *(uint4*)base          = *(const uint4*)&hv[0];
        *(uint4*)(base + 1024) = *(const uint4*)&hv[8];   // chunk c+1
    }

    __syncthreads();
#pragma unroll
    for (int r = 0; r < 16; ++r)
        snf[r][t] = acc[r];                // snf now holds h
    __syncthreads();

    const int rr = t >> 3;                 // node-in-block 0..15
    const int hb = (t & 7) * 2;
    const int slot = (rr & 1) | (((rr >> 3) & 1) << 1) | (((rr >> 1) & 3) << 2);
#pragma unroll
    for (int p = 0; p < 2; ++p) {
        const int h = hb + p;
        const float* hv = &snf[rr][h * Cc];
        const float* ap = a + h * 2 * Cc;
        float lp = 0.f, lc = 0.f;
#pragma unroll
        for (int c = 0; c < Cc; ++c) {
            lp = fmaf(hv[c], ap[c],      lp);
            lc = fmaf(hv[c], ap[Cc + c], lc);
        }
        lp *= LOG2E; lc *= LOG2E;
        const int n = r0 + rr;
        g_lp[n * Hh + h] = lp;
        const size_t fbase = ((size_t)b * Hh + h) * Nn + n0 + slot;
        g_Fa [fbase] = __float2half(ex2f(lc));
        g_Fpa[fbase] = __float2half(ex2f(0.2f * lc));
        sred[h][rr] = lc;
    }
    __syncthreads();
    if (t < Hh) {
        float m = sred[t][0];
#pragma unroll
        for (int r = 1; r < 16; ++r) m = fmaxf(m, sred[t][r]);
        atomicMax(&g_mxu[b * Hh + t], encf(m));
    }
}

// ---------------------------------------------------------------
// Kernel C: fused softmax-attention via mma.m16n8k16.
// H read via coalesced LDG from L2 (chunk-major, no staging).
// adj fp32 via 4-stage TMA ring, prefetch distance 3.
// ---------------------------------------------------------------
__global__ __launch_bounds__(512, 2) void k_main(
        const __grid_constant__ CUtensorMap tmaf,
        float* __restrict__ out, int copy_adj) {
    extern __shared__ __align__(128) char smem[];
    __shared__ __align__(8) unsigned long long mbar[4];

    const int t    = threadIdx.x;
    const int warp = t >> 5;
    const int lane = t & 31;
    const int gid  = lane >> 2;   // 0..7
    const int tig  = lane & 3;    // 0..3
    const int hh   = warp;

    const int b  = blockIdx.x >> 7;
    const int i0 = (blockIdx.x & 127) * 16;
    const size_t bN = (size_t)b * Nn;

    if (t < 4) MBAR_INIT(s2u(&mbar[t]), 1);
    asm volatile("fence.proxy.async.shared::cta;" ::: "memory");
    __syncthreads();

    auto issue_tile = [&](int jb) {
        const int st = jb & 3;
        const uint32_t mb = s2u(&mbar[st]);
        MBAR_EXPECT(mb, TILE_BYTES);
        const uint32_t dst = s2u(smem + SO_F + st * SF_STRIDE);
        TMA2D(dst,        &tmaf, jb * 128,      (int)(bN + i0), mb);
        TMA2D(dst + 4096, &tmaf, jb * 128 + 64, (int)(bN + i0), mb);
    };

    // per-row factors E = 2^(lp-m), E' = 2^(0.2lp-m)
    __half2 E0, E0p, E1, E1p;
    {
        const float mx  = decf(g_mxu[b * Hh + hh]);
        const float lp0 = g_lp[(bN + i0 + gid)     * Hh + hh];
        const float lp1 = g_lp[(bN + i0 + gid + 8) * Hh + hh];
        const float s0 = lp0 + mx, s1 = lp1 + mx;
        const float m0 = fmaxf(s0, 0.2f * s0);
        const float m1 = fmaxf(s1, 0.2f * s1);
        E0  = __float2half2_rn(ex2f(lp0 - m0));
        E0p = __float2half2_rn(ex2f(0.2f * lp0 - m0));
        E1  = __float2half2_rn(ex2f(lp1 - m1));
        E1p = __float2half2_rn(ex2f(0.2f * lp1 - m1));
    }

    const __half* Fab = g_Fa  + ((size_t)b * Hh + hh) * Nn + 4 * tig;
    const __half* Fpb = g_Fpa + ((size_t)b * Hh + hh) * Nn + 4 * tig;
    // H base (global, chunk-major): warp reads 128B contiguous per chunk
    const char* Hbase = (const char*)g_hT2
        + (size_t)b * NJB * 32768 + (hh * 8 + gid) * 16 + tig * 4;

    float dn0 = 0.f, dn1 = 0.f, dn2 = 0.f, dn3 = 0.f;
    float dd0 = 0.f, dd1 = 0.f, dd2 = 0.f, dd3 = 0.f;
    const uint32_t ONES = 0x3C003C00u;

    // convert-step mapping: thread t handles floats [4t, 4t+4)
    const int cv_row = (t >> 4) & 15;
    const int cv_c   = (t >> 8) * 8 + ((t & 15) >> 1);   // dest chunk
    const int cv_w   = (t & 1) * 8;                      // byte offset in 16B row-cell
    float* cv_tail = copy_adj
        ? out + (size_t)Bn * Nn * HC + (bN + i0 + cv_row) * (size_t)Nn
              + (t >> 8) * 64 + (t & 15) * 4
        : nullptr;

    if (t == 0) { issue_tile(0); issue_tile(1); issue_tile(2); }

    for (int jb = 0; jb < NJB; ++jb) {
        const int st = jb & 3;
        char* const sFb = smem + SO_F + st * SF_STRIDE;
        char* const sAb = smem + SO_A + (jb & 1) * SA_STRIDE;

        mbar_wait(s2u(&mbar[st]), (jb >> 2) & 1);

        // ---- convert fp32 adj tile -> chunk-major fp16 (padded), + tail ----
        {
            const float4 v = *(const float4*)(sFb + 16 * t);
            uint2 hp;
            hp.x = packh2(v.x, v.y);
            hp.y = packh2(v.z, v.w);
            *(uint2*)(sAb + cv_c * SA_CH + cv_row * 16 + cv_w) = hp;
            if (copy_adj) *(float4*)(cv_tail + jb * 128) = v;
        }
        __syncthreads();
        if (jb + 3 < NJB && t == 0) issue_tile(jb + 3);

        // per-thread bases (all inner offsets immediate)
        const char* Hp  = Hbase + (size_t)jb * 32768;
        const char* Ap0 = sAb + gid * 16       + tig * 4;
        const char* Ap1 = sAb + (gid + 8) * 16 + tig * 4;
        const __half* Faj = Fab + jb * 128;
        const __half* Fpj = Fpb + jb * 128;

#pragma unroll
        for (int ks = 0; ks < 8; ++ks) {
            const uint2 fa  = *(const uint2*)(Faj + ks * 16);
            const uint2 fpa = *(const uint2*)(Fpj + ks * 16);

            const uint32_t bh0 = *(const uint32_t*)(Hp + (2 * ks)     * 2048);
            const uint32_t bh1 = *(const uint32_t*)(Hp + (2 * ks + 1) * 2048);

            const __half2 m00 = *(const __half2*)(Ap0 + (2 * ks)     * SA_CH);
            const __half2 m01 = *(const __half2*)(Ap0 + (2 * ks + 1) * SA_CH);
            const __half2 m10 = *(const __half2*)(Ap1 + (2 * ks)     * SA_CH);
            const __half2 m11 = *(const __half2*)(Ap1 + (2 * ks + 1) * SA_CH);

            const __half2 w0lo = __hmax2(__hmul2(b2h(fa.x),  E0),  __hmul2(b2h(fpa.x), E0p));
            const __half2 w1lo = __hmax2(__hmul2(b2h(fa.x),  E1),  __hmul2(b2h(fpa.x), E1p));
            const __half2 w0hi = __hmax2(__hmul2(b2h(fa.y),  E0),  __hmul2(b2h(fpa.y), E0p));
            const __half2 w1hi = __hmax2(__hmul2(b2h(fa.y),  E1),  __hmul2(b2h(fpa.y), E1p));

            const uint32_t ra0 = h2b(__hmul2(w0lo, m00));
            const uint32_t ra1 = h2b(__hmul2(w1lo, m10));
            const uint32_t ra2 = h2b(__hmul2(w0hi, m01));
            const uint32_t ra3 = h2b(__hmul2(w1hi, m11));

            mma16816(dn0, dn1, dn2, dn3, ra0, ra1, ra2, ra3, bh0, bh1);
            mma16816(dd0, dd1, dd2, dd3, ra0, ra1, ra2, ra3, ONES, ONES);
        }
        __syncthreads();     // compute(jb) done before convert(jb+1) rewrites sA
    }

    // ---- epilogue: divide and store ----
    {
        const float inv0 = 1.0f / dd0;
        const float inv1 = 1.0f / dd2;
        float2 o0 = make_float2(dn0 * inv0, dn1 * inv0);
        float2 o1 = make_float2(dn2 * inv1, dn3 * inv1);
        *(float2*)(out + (bN + i0 + gid)     * HC + hh * Cc + 2 * tig) = o0;
        *(float2*)(out + (bN + i0 + gid + 8) * HC + hh * Cc + 2 * tig) = o1;
    }
}

// ---------------------------------------------------------------
extern "C" void kernel_launch(void* const* d_in, const int* in_sizes, int n_in,
                              void* d_out, int out_size) {
    const float* nf   = (const float*)d_in[0];
    const float* adj  = (const float*)d_in[1];
    const float* W    = (const float*)d_in[2];
    const float* bias = (const float*)d_in[3];
    const float* a    = (const float*)d_in[4];
    float* out = (float*)d_out;

    const long long outel = (long long)Bn * Nn * HC;        // 524288
    const long long adjel = (long long)Bn * Nn * Nn;        // 8388608
    const int copy_adj = ((long long)out_size >= outel + adjel) ? 1 : 0;

    // ---- TMA descriptor (adj fp32 only) ----
    PFN_tmencode pfn = nullptr;
    cudaDriverEntryPointQueryResult qr;
    cudaGetDriverEntryPoint("cuTensorMapEncodeTiled", (void**)&pfn,
                            cudaEnableDefault, &qr);

    void* p_mxu = nullptr;
    cudaGetSymbolAddress(&p_mxu, g_mxu);

    CUtensorMap tmaf;
    {
        cuuint64_t dims[2]    = { (cuuint64_t)Nn, (cuuint64_t)(Bn * Nn) };
        cuuint64_t strides[1] = { (cuuint64_t)Nn * 4 };
        cuuint32_t box[2]     = { 64, 16 };
        cuuint32_t estr[2]    = { 1, 1 };
        pfn(&tmaf, CU_TENSOR_MAP_DATA_TYPE_FLOAT32, 2, (void*)adj, dims, strides,
            box, estr, CU_TENSOR_MAP_INTERLEAVE_NONE, CU_TENSOR_MAP_SWIZZLE_NONE,
            CU_TENSOR_MAP_L2_PROMOTION_L2_128B, CU_TENSOR_MAP_FLOAT_OOB_FILL_NONE);
    }

    cudaFuncSetAttribute(k_main, cudaFuncAttributeMaxDynamicSharedMemorySize,
                         SMEM_BYTES);

    cudaMemsetAsync(p_mxu, 0, Bn * Hh * sizeof(unsigned));
    k_proj<<<Bn * Nn / 16, 128>>>(nf, W, bias, a);
    k_main<<<Bn * (Nn / 16), 512, SMEM_BYTES>>>(tmaf, out, copy_adj);
}

// round 14
// speedup vs baseline: 2.5524x; 1.0571x over previous
#include <cuda_runtime.h>
#include <cuda_fp16.h>
#include <cuda.h>
#include <cstdint>

#define Bn   2
#define Nn   2048
#define CIN  128
#define Hh   16
#define Cc   8
#define HC   128
#define LOG2E 1.4426950408889634f
#define NJB  16          // j-blocks of 128

// smem (bytes): adj fp32 ring 4x8192 | adj fp16 2x4352 (chunk stride 272)
#define SO_F    0
#define SF_STRIDE 8192
#define SO_A    (4 * 8192)
#define SA_STRIDE 4352
#define SA_CH   272
#define SMEM_BYTES (4 * 8192 + 2 * 4352)
#define TILE_BYTES 8192          // per-stage expect_tx

// driver-API typedef (not provided by this toolchain's cudaTypedefs.h)
typedef CUresult (*PFN_tmencode)(
    CUtensorMap*, CUtensorMapDataType, cuuint32_t, void*,
    const cuuint64_t*, const cuuint64_t*, const cuuint32_t*, const cuuint32_t*,
    CUtensorMapInterleave, CUtensorMapSwizzle, CUtensorMapL2promotion,
    CUtensorMapFloatOOBfill);

// ---- device scratch ----
// g_hT2: per (b, j-block): [chunk 0..15][f 0..127][8 halves]  (32KB contiguous)
__device__ __half   g_hT2[Bn * HC * Nn];
__device__ float    g_lp [Bn * Nn * Hh];   // lp * log2e
__device__ __half   g_Fa [Bn * Hh * Nn];   // 2^lc, fragment-permuted per 16-group
__device__ __half   g_Fpa[Bn * Hh * Nn];   // 2^(0.2lc), fragment-permuted

// ---- PTX helpers ----
static __device__ __forceinline__ uint32_t s2u(const void* p) {
    return (uint32_t)__cvta_generic_to_shared(p);
}
static __device__ __forceinline__ float ex2f(float x) {
    float r; asm("ex2.approx.f32 %0, %1;" : "=f"(r) : "f"(x)); return r;
}
static __device__ __forceinline__ uint32_t packh2(float lo, float hi) {
    uint32_t d; asm("cvt.rn.f16x2.f32 %0, %1, %2;" : "=r"(d) : "f"(hi), "f"(lo)); return d;
}
static __device__ __forceinline__ uint32_t h2b(__half2 v) {
    return *reinterpret_cast<uint32_t*>(&v);
}
static __device__ __forceinline__ __half2 b2h(uint32_t u) {
    return *reinterpret_cast<__half2*>(&u);
}
static __device__ __forceinline__ void mma16816(float& d0, float& d1, float& d2, float& d3,
                                                uint32_t a0, uint32_t a1, uint32_t a2, uint32_t a3,
                                                uint32_t b0, uint32_t b1) {
    asm("mma.sync.aligned.m16n8k16.row.col.f32.f16.f16.f32 "
        "{%0,%1,%2,%3}, {%4,%5,%6,%7}, {%8,%9}, {%0,%1,%2,%3};"
        : "+f"(d0), "+f"(d1), "+f"(d2), "+f"(d3)
        : "r"(a0), "r"(a1), "r"(a2), "r"(a3), "r"(b0), "r"(b1));
}
#define MBAR_INIT(mb, cnt) \
    asm volatile("mbarrier.init.shared.b64 [%0], %1;" :: "r"(mb), "r"(cnt) : "memory")
#define MBAR_EXPECT(mb, bytes) \
    asm volatile("mbarrier.arrive.expect_tx.shared.b64 _, [%0], %1;" :: "r"(mb), "r"(bytes) : "memory")
#define TMA2D(smem, map, x, y, mb) \
    asm volatile("cp.async.bulk.tensor.2d.shared::cta.global.tile.mbarrier::complete_tx::bytes " \
                 "[%0], [%1, {%2, %3}], [%4];" \
                 :: "r"(smem), "l"(map), "r"(x), "r"(y), "r"(mb) : "memory")
static __device__ __forceinline__ void mbar_wait(uint32_t mb, uint32_t parity) {
    asm volatile(
        "{\n\t.reg .pred P;\n\t"
        "WL_%=:\n\t"
        "mbarrier.try_wait.parity.acquire.cta.shared::cta.b64 P, [%0], %1, 0x989680;\n\t"
        "@P bra.uni WD_%=;\n\t"
        "bra.uni WL_%=;\n\t"
        "WD_%=:\n\t}"
        :: "r"(mb), "r"(parity) : "memory");
}

// ---------------------------------------------------------------
// Kernel B: projection + per-node logits, fused.
// hT2 chunk-major; F/F' fragment-permuted. No global max needed.
// ---------------------------------------------------------------
__global__ __launch_bounds__(128) void k_proj(const float* __restrict__ nf,
                                              const float* __restrict__ W,
                                              const float* __restrict__ bias,
                                              const float* __restrict__ a) {
    __shared__ float snf[16][132];
    const int t  = threadIdx.x;
    const int r0 = blockIdx.x * 16;
#pragma unroll
    for (int r = 0; r < 16; ++r)
        snf[r][t] = nf[(size_t)(r0 + r) * CIN + t];
    __syncthreads();

    float acc[16];
    const float bv = bias[t];
#pragma unroll
    for (int r = 0; r < 16; ++r) acc[r] = bv;

    for (int k4 = 0; k4 < CIN / 4; ++k4) {
        const float w0 = W[(k4 * 4 + 0) * HC + t];
        const float w1 = W[(k4 * 4 + 1) * HC + t];
        const float w2 = W[(k4 * 4 + 2) * HC + t];
        const float w3 = W[(k4 * 4 + 3) * HC + t];
#pragma unroll
        for (int r = 0; r < 16; ++r) {
            const float4 s = *(const float4*)&snf[r][k4 * 4];
            acc[r] = fmaf(s.x, w0, acc[r]);
            acc[r] = fmaf(s.y, w1, acc[r]);
            acc[r] = fmaf(s.z, w2, acc[r]);
            acc[r] = fmaf(s.w, w3, acc[r]);
        }
    }

    const int b  = r0 >> 11;
    const int n0 = r0 & (Nn - 1);

    // hT2 write (chunk-major): thread t == feature f; 16 n = chunks c, c+1.
    {
        __half hv[16];
#pragma unroll
        for (int r = 0; r < 16; ++r) hv[r] = __float2half(acc[r]);
        const int jb = n0 >> 7;
        const int c  = (n0 & 127) >> 3;
        __half* base = g_hT2 + ((((size_t)b * NJB + jb) * 16 + c) * 128 + t) * 8;
        *(uint4*)base          = *(const uint4*)&hv[0];
        *(uint4*)(base + 1024) = *(const uint4*)&hv[8];
    }

    __syncthreads();
#pragma unroll
    for (int r = 0; r < 16; ++r)
        snf[r][t] = acc[r];                // snf now holds h
    __syncthreads();

    const int rr = t >> 3;                 // node-in-block 0..15
    const int hb = (t & 7) * 2;
    const int slot = (rr & 1) | (((rr >> 3) & 1) << 1) | (((rr >> 1) & 3) << 2);
#pragma unroll
    for (int p = 0; p < 2; ++p) {
        const int h = hb + p;
        const float* hv = &snf[rr][h * Cc];
        const float* ap = a + h * 2 * Cc;
        float lp = 0.f, lc = 0.f;
#pragma unroll
        for (int c = 0; c < Cc; ++c) {
            lp = fmaf(hv[c], ap[c],      lp);
            lc = fmaf(hv[c], ap[Cc + c], lc);
        }
        lp *= LOG2E; lc *= LOG2E;
        const int n = r0 + rr;
        g_lp[n * Hh + h] = lp;
        const size_t fbase = ((size_t)b * Hh + h) * Nn + n0 + slot;
        g_Fa [fbase] = __float2half(ex2f(lc));
        g_Fpa[fbase] = __float2half(ex2f(0.2f * lc));
    }
}

// ---------------------------------------------------------------
// Kernel C: fused softmax-attention via mma.m16n8k16.
// 256 threads = 8 heads; 2 head-groups per i-tile; 4 blocks/SM.
// H via coalesced LDG (L2); adj via 4-stage TMA ring, dist 3.
// Stabilizer m_i = leaky(lp_i) (no global max needed).
// ---------------------------------------------------------------
__global__ __launch_bounds__(256, 4) void k_main(
        const __grid_constant__ CUtensorMap tmaf,
        float* __restrict__ out, int copy_adj) {
    extern __shared__ __align__(128) char smem[];
    __shared__ __align__(8) unsigned long long mbar[4];

    const int t    = threadIdx.x;
    const int warp = t >> 5;
    const int lane = t & 31;
    const int gid  = lane >> 2;   // 0..7
    const int tig  = lane & 3;    // 0..3

    const int bx = blockIdx.x;
    const int b  = bx >> 8;
    const int i0 = ((bx & 255) >> 1) * 16;
    const int hp = bx & 1;
    const int hh = hp * 8 + warp;
    const size_t bN = (size_t)b * Nn;

    if (t < 4) MBAR_INIT(s2u(&mbar[t]), 1);
    asm volatile("fence.proxy.async.shared::cta;" ::: "memory");
    __syncthreads();

    auto issue_tile = [&](int jb) {
        const int st = jb & 3;
        const uint32_t mb = s2u(&mbar[st]);
        MBAR_EXPECT(mb, TILE_BYTES);
        const uint32_t dst = s2u(smem + SO_F + st * SF_STRIDE);
        TMA2D(dst,        &tmaf, jb * 128,      (int)(bN + i0), mb);
        TMA2D(dst + 4096, &tmaf, jb * 128 + 64, (int)(bN + i0), mb);
    };

    // per-row factors, stabilized by m = leaky(lp)
    __half2 E0, E0p, E1, E1p;
    {
        const float lp0 = g_lp[(bN + i0 + gid)     * Hh + hh];
        const float lp1 = g_lp[(bN + i0 + gid + 8) * Hh + hh];
        const float m0 = fmaxf(lp0, 0.2f * lp0);
        const float m1 = fmaxf(lp1, 0.2f * lp1);
        E0  = __float2half2_rn(ex2f(lp0 - m0));
        E0p = __float2half2_rn(ex2f(0.2f * lp0 - m0));
        E1  = __float2half2_rn(ex2f(lp1 - m1));
        E1p = __float2half2_rn(ex2f(0.2f * lp1 - m1));
    }

    const __half* Fab = g_Fa  + ((size_t)b * Hh + hh) * Nn + 4 * tig;
    const __half* Fpb = g_Fpa + ((size_t)b * Hh + hh) * Nn + 4 * tig;
    const char* Hbase = (const char*)g_hT2
        + (size_t)b * NJB * 32768 + (hh * 8 + gid) * 16 + tig * 4;

    float dn0 = 0.f, dn1 = 0.f, dn2 = 0.f, dn3 = 0.f;
    float dd0 = 0.f, dd1 = 0.f, dd2 = 0.f, dd3 = 0.f;
    const uint32_t ONES = 0x3C003C00u;

    // convert-step mapping (256 thr, 2 float4 each)
    const int cv_row = (t >> 4) & 15;
    const int cv_c   = (t & 15) >> 1;
    const int cv_w   = (t & 1) * 8;
    const int do_tail = copy_adj && (hp == 0);
    float* cv_tail = do_tail
        ? out + (size_t)Bn * Nn * HC + (bN + i0 + cv_row) * (size_t)Nn + (t & 15) * 4
        : nullptr;

    if (t == 0) { issue_tile(0); issue_tile(1); issue_tile(2); }

    for (int jb = 0; jb < NJB; ++jb) {
        const int st = jb & 3;
        char* const sFb = smem + SO_F + st * SF_STRIDE;
        char* const sAb = smem + SO_A + (jb & 1) * SA_STRIDE;

        mbar_wait(s2u(&mbar[st]), (jb >> 2) & 1);

        // ---- convert fp32 adj tile -> chunk-major fp16 (padded), + tail ----
        {
            const float4 v0 = *(const float4*)(sFb + 16 * t);
            const float4 v1 = *(const float4*)(sFb + 16 * t + 4096);
            uint2 p0, p1;
            p0.x = packh2(v0.x, v0.y); p0.y = packh2(v0.z, v0.w);
            p1.x = packh2(v1.x, v1.y); p1.y = packh2(v1.z, v1.w);
            *(uint2*)(sAb + cv_c       * SA_CH + cv_row * 16 + cv_w) = p0;
            *(uint2*)(sAb + (cv_c + 8) * SA_CH + cv_row * 16 + cv_w) = p1;
            if (do_tail) {
                *(float4*)(cv_tail + jb * 128)      = v0;
                *(float4*)(cv_tail + jb * 128 + 64) = v1;
            }
        }
        __syncthreads();
        if (jb + 3 < NJB && t == 0) issue_tile(jb + 3);

        const char* Hp  = Hbase + (size_t)jb * 32768;
        const char* Ap0 = sAb + gid * 16       + tig * 4;
        const char* Ap1 = sAb + (gid + 8) * 16 + tig * 4;
        const __half* Faj = Fab + jb * 128;
        const __half* Fpj = Fpb + jb * 128;

#pragma unroll
        for (int ks = 0; ks < 8; ++ks) {
            const uint2 fa  = *(const uint2*)(Faj + ks * 16);
            const uint2 fpa = *(const uint2*)(Fpj + ks * 16);

            const uint32_t bh0 = *(const uint32_t*)(Hp + (2 * ks)     * 2048);
            const uint32_t bh1 = *(const uint32_t*)(Hp + (2 * ks + 1) * 2048);

            const __half2 m00 = *(const __half2*)(Ap0 + (2 * ks)     * SA_CH);
            const __half2 m01 = *(const __half2*)(Ap0 + (2 * ks + 1) * SA_CH);
            const __half2 m10 = *(const __half2*)(Ap1 + (2 * ks)     * SA_CH);
            const __half2 m11 = *(const __half2*)(Ap1 + (2 * ks + 1) * SA_CH);

            const __half2 w0lo = __hmax2(__hmul2(b2h(fa.x),  E0),  __hmul2(b2h(fpa.x), E0p));
            const __half2 w1lo = __hmax2(__hmul2(b2h(fa.x),  E1),  __hmul2(b2h(fpa.x), E1p));
            const __half2 w0hi = __hmax2(__hmul2(b2h(fa.y),  E0),  __hmul2(b2h(fpa.y), E0p));
            const __half2 w1hi = __hmax2(__hmul2(b2h(fa.y),  E1),  __hmul2(b2h(fpa.y), E1p));

            const uint32_t ra0 = h2b(__hmul2(w0lo, m00));
            const uint32_t ra1 = h2b(__hmul2(w1lo, m10));
            const uint32_t ra2 = h2b(__hmul2(w0hi, m01));
            const uint32_t ra3 = h2b(__hmul2(w1hi, m11));

            mma16816(dn0, dn1, dn2, dn3, ra0, ra1, ra2, ra3, bh0, bh1);
            mma16816(dd0, dd1, dd2, dd3, ra0, ra1, ra2, ra3, ONES, ONES);
        }
    }

    // ---- epilogue: divide and store ----
    {
        const float inv0 = 1.0f / dd0;
        const float inv1 = 1.0f / dd2;
        float2 o0 = make_float2(dn0 * inv0, dn1 * inv0);
        float2 o1 = make_float2(dn2 * inv1, dn3 * inv1);
        *(float2*)(out + (bN + i0 + gid)     * HC + hh * Cc + 2 * tig) = o0;
        *(float2*)(out + (bN + i0 + gid + 8) * HC + hh * Cc + 2 * tig) = o1;
    }
}

// ---------------------------------------------------------------
extern "C" void kernel_launch(void* const* d_in, const int* in_sizes, int n_in,
                              void* d_out, int out_size) {
    const float* nf   = (const float*)d_in[0];
    const float* adj  = (const float*)d_in[1];
    const float* W    = (const float*)d_in[2];
    const float* bias = (const float*)d_in[3];
    const float* a    = (const float*)d_in[4];
    float* out = (float*)d_out;

    const long long outel = (long long)Bn * Nn * HC;        // 524288
    const long long adjel = (long long)Bn * Nn * Nn;        // 8388608
    const int copy_adj = ((long long)out_size >= outel + adjel) ? 1 : 0;

    // ---- TMA descriptor (adj fp32) ----
    PFN_tmencode pfn = nullptr;
    cudaDriverEntryPointQueryResult qr;
    cudaGetDriverEntryPoint("cuTensorMapEncodeTiled", (void**)&pfn,
                            cudaEnableDefault, &qr);

    CUtensorMap tmaf;
    {
        cuuint64_t dims[2]    = { (cuuint64_t)Nn, (cuuint64_t)(Bn * Nn) };
        cuuint64_t strides[1] = { (cuuint64_t)Nn * 4 };
        cuuint32_t box[2]     = { 64, 16 };
        cuuint32_t estr[2]    = { 1, 1 };
        pfn(&tmaf, CU_TENSOR_MAP_DATA_TYPE_FLOAT32, 2, (void*)adj, dims, strides,
            box, estr, CU_TENSOR_MAP_INTERLEAVE_NONE, CU_TENSOR_MAP_SWIZZLE_NONE,
            CU_TENSOR_MAP_L2_PROMOTION_L2_128B, CU_TENSOR_MAP_FLOAT_OOB_FILL_NONE);
    }

    cudaFuncSetAttribute(k_main, cudaFuncAttributeMaxDynamicSharedMemorySize,
                         SMEM_BYTES);

    k_proj<<<Bn * Nn / 16, 128>>>(nf, W, bias, a);
    k_main<<<Bn * 256, 256, SMEM_BYTES>>>(tmaf, out, copy_adj);
}

// round 15
// speedup vs baseline: 2.6420x; 1.0351x over previous
#include <cuda_runtime.h>
#include <cuda_fp16.h>
#include <cuda.h>
#include <cstdint>

#define Bn   2
#define Nn   2048
#define CIN  128
#define Hh   16
#define Cc   8
#define HC   128
#define LOG2E 1.4426950408889634f
#define NJB  16          // j-blocks of 128

// smem (bytes): adj fp32 ring 4x8192 | adj fp16 (paired layout) 2x4096
#define SO_F    0
#define SF_STRIDE 8192
#define SO_A    (4 * 8192)
#define SA_STRIDE 4096
#define SMEM_BYTES (4 * 8192 + 2 * 4096)
#define TILE_BYTES 8192          // per-stage expect_tx

// driver-API typedef (not provided by this toolchain's cudaTypedefs.h)
typedef CUresult (*PFN_tmencode)(
    CUtensorMap*, CUtensorMapDataType, cuuint32_t, void*,
    const cuuint64_t*, const cuuint64_t*, const cuuint32_t*, const cuuint32_t*,
    CUtensorMapInterleave, CUtensorMapSwizzle, CUtensorMapL2promotion,
    CUtensorMapFloatOOBfill);

// ---- device scratch ----
// g_hT3: per (b, jb): [kpair 0..7][f 0..127][32B: c0w0 c1w0 c0w1 c1w1 ...]
__device__ __half   g_hT3[Bn * HC * Nn];
__device__ float    g_lp [Bn * Nn * Hh];       // lp * log2e
// g_FF2: per (b,h): per 16-group: [tig 0..3][8B Fa slots | 8B Fpa slots]
__device__ __half   g_FF2[Bn * Hh * Nn * 2];

// ---- PTX helpers ----
static __device__ __forceinline__ uint32_t s2u(const void* p) {
    return (uint32_t)__cvta_generic_to_shared(p);
}
static __device__ __forceinline__ float ex2f(float x) {
    float r; asm("ex2.approx.f32 %0, %1;" : "=f"(r) : "f"(x)); return r;
}
static __device__ __forceinline__ uint32_t packh2(float lo, float hi) {
    uint32_t d; asm("cvt.rn.f16x2.f32 %0, %1, %2;" : "=r"(d) : "f"(hi), "f"(lo)); return d;
}
static __device__ __forceinline__ uint32_t h2b(__half2 v) {
    return *reinterpret_cast<uint32_t*>(&v);
}
static __device__ __forceinline__ __half2 b2h(uint32_t u) {
    return *reinterpret_cast<__half2*>(&u);
}
static __device__ __forceinline__ void mma16816(float& d0, float& d1, float& d2, float& d3,
                                                uint32_t a0, uint32_t a1, uint32_t a2, uint32_t a3,
                                                uint32_t b0, uint32_t b1) {
    asm("mma.sync.aligned.m16n8k16.row.col.f32.f16.f16.f32 "
        "{%0,%1,%2,%3}, {%4,%5,%6,%7}, {%8,%9}, {%0,%1,%2,%3};"
        : "+f"(d0), "+f"(d1), "+f"(d2), "+f"(d3)
        : "r"(a0), "r"(a1), "r"(a2), "r"(a3), "r"(b0), "r"(b1));
}
#define MBAR_INIT(mb, cnt) \
    asm volatile("mbarrier.init.shared.b64 [%0], %1;" :: "r"(mb), "r"(cnt) : "memory")
#define MBAR_EXPECT(mb, bytes) \
    asm volatile("mbarrier.arrive.expect_tx.shared.b64 _, [%0], %1;" :: "r"(mb), "r"(bytes) : "memory")
#define TMA2D(smem, map, x, y, mb) \
    asm volatile("cp.async.bulk.tensor.2d.shared::cta.global.tile.mbarrier::complete_tx::bytes " \
                 "[%0], [%1, {%2, %3}], [%4];" \
                 :: "r"(smem), "l"(map), "r"(x), "r"(y), "r"(mb) : "memory")
#define TMA2D_ST(map, x, y, smem) \
    asm volatile("cp.async.bulk.tensor.2d.global.shared::cta.tile.bulk_group " \
                 "[%0, {%1, %2}], [%3];" \
                 :: "l"(map), "r"(x), "r"(y), "r"(smem) : "memory")
#define TMA_ST_COMMIT() asm volatile("cp.async.bulk.commit_group;" ::: "memory")
#define TMA_ST_WAIT(n)  asm volatile("cp.async.bulk.wait_group %0;" :: "n"(n) : "memory")
static __device__ __forceinline__ void mbar_wait(uint32_t mb, uint32_t parity) {
    asm volatile(
        "{\n\t.reg .pred P;\n\t"
        "WL_%=:\n\t"
        "mbarrier.try_wait.parity.acquire.cta.shared::cta.b64 P, [%0], %1, 0x989680;\n\t"
        "@P bra.uni WD_%=;\n\t"
        "bra.uni WL_%=;\n\t"
        "WD_%=:\n\t}"
        :: "r"(mb), "r"(parity) : "memory");
}

// ---------------------------------------------------------------
// Kernel B: projection + per-node logits, fused.
// hT3 pair-interleaved; FF2 fragment-permuted interleaved.
// ---------------------------------------------------------------
__global__ __launch_bounds__(128) void k_proj(const float* __restrict__ nf,
                                              const float* __restrict__ W,
                                              const float* __restrict__ bias,
                                              const float* __restrict__ a) {
    __shared__ float snf[16][132];
    const int t  = threadIdx.x;
    const int r0 = blockIdx.x * 16;
#pragma unroll
    for (int r = 0; r < 16; ++r)
        snf[r][t] = nf[(size_t)(r0 + r) * CIN + t];
    __syncthreads();

    float acc[16];
    const float bv = bias[t];
#pragma unroll
    for (int r = 0; r < 16; ++r) acc[r] = bv;

    for (int k4 = 0; k4 < CIN / 4; ++k4) {
        const float w0 = W[(k4 * 4 + 0) * HC + t];
        const float w1 = W[(k4 * 4 + 1) * HC + t];
        const float w2 = W[(k4 * 4 + 2) * HC + t];
        const float w3 = W[(k4 * 4 + 3) * HC + t];
#pragma unroll
        for (int r = 0; r < 16; ++r) {
            const float4 s = *(const float4*)&snf[r][k4 * 4];
            acc[r] = fmaf(s.x, w0, acc[r]);
            acc[r] = fmaf(s.y, w1, acc[r]);
            acc[r] = fmaf(s.z, w2, acc[r]);
            acc[r] = fmaf(s.w, w3, acc[r]);
        }
    }

    const int b  = r0 >> 11;
    const int n0 = r0 & (Nn - 1);
    const int jb = n0 >> 7;
    const int kp = (n0 & 127) >> 4;        // kpair 0..7

    // hT3 write: pair-interleave words of chunks c0 (n 0..7) and c1 (n 8..15)
    {
        __half hv[16], iv[16];
#pragma unroll
        for (int r = 0; r < 16; ++r) hv[r] = __float2half(acc[r]);
#pragma unroll
        for (int w = 0; w < 4; ++w) {
            iv[4 * w + 0] = hv[2 * w];
            iv[4 * w + 1] = hv[2 * w + 1];
            iv[4 * w + 2] = hv[8 + 2 * w];
            iv[4 * w + 3] = hv[9 + 2 * w];
        }
        __half* base = g_hT3 + ((((size_t)(b * NJB + jb)) * 8 + kp) * 128 + t) * 16;
        *(uint4*)base       = *(const uint4*)&iv[0];
        *(uint4*)(base + 8) = *(const uint4*)&iv[8];
    }

    __syncthreads();
#pragma unroll
    for (int r = 0; r < 16; ++r)
        snf[r][t] = acc[r];                // snf now holds h
    __syncthreads();

    const int rr = t >> 3;                 // node-in-block 0..15
    const int hb = (t & 7) * 2;
    const int slot = (rr & 1) | (((rr >> 3) & 1) << 1) | (((rr >> 1) & 3) << 2);
    const int tigs = slot >> 2, pos = slot & 3;
    const int g = n0 >> 4;                 // 16-group index
#pragma unroll
    for (int p = 0; p < 2; ++p) {
        const int h = hb + p;
        const float* hv = &snf[rr][h * Cc];
        const float* ap = a + h * 2 * Cc;
        float lp = 0.f, lc = 0.f;
#pragma unroll
        for (int c = 0; c < Cc; ++c) {
            lp = fmaf(hv[c], ap[c],      lp);
            lc = fmaf(hv[c], ap[Cc + c], lc);
        }
        lp *= LOG2E; lc *= LOG2E;
        g_lp[(r0 + rr) * Hh + h] = lp;
        __half* fb = g_FF2 + (((size_t)b * Hh + h) * (Nn / 16) + g) * 32;
        fb[tigs * 8 + pos]     = __float2half(ex2f(lc));
        fb[tigs * 8 + 4 + pos] = __float2half(ex2f(0.2f * lc));
    }
}

// ---------------------------------------------------------------
// Kernel C: fused softmax-attention via mma.m16n8k16.
// Paired layouts: 1 LDG.64 (H) + 1 LDG.128 (F) + 2 LDS.64 (adj) per k-step.
// Tail copy via TMA store from the staged fp32 tile.
// ---------------------------------------------------------------
__global__ __launch_bounds__(256, 4) void k_main(
        const __grid_constant__ CUtensorMap tmaf,
        const __grid_constant__ CUtensorMap tmat,
        float* __restrict__ out, int copy_adj) {
    extern __shared__ __align__(128) char smem[];
    __shared__ __align__(8) unsigned long long mbar[4];

    const int t    = threadIdx.x;
    const int warp = t >> 5;
    const int lane = t & 31;
    const int gid  = lane >> 2;   // 0..7
    const int tig  = lane & 3;    // 0..3

    const int bx = blockIdx.x;
    const int b  = bx >> 8;
    const int i0 = ((bx & 255) >> 1) * 16;
    const int hp = bx & 1;
    const int hh = hp * 8 + warp;
    const size_t bN = (size_t)b * Nn;
    const int yrow = (int)(bN + i0);

    if (t < 4) MBAR_INIT(s2u(&mbar[t]), 1);
    asm volatile("fence.proxy.async.shared::cta;" ::: "memory");
    __syncthreads();

    auto issue_tile = [&](int jb) {
        const int st = jb & 3;
        const uint32_t mb = s2u(&mbar[st]);
        MBAR_EXPECT(mb, TILE_BYTES);
        const uint32_t dst = s2u(smem + SO_F + st * SF_STRIDE);
        TMA2D(dst,        &tmaf, jb * 128,      yrow, mb);
        TMA2D(dst + 4096, &tmaf, jb * 128 + 64, yrow, mb);
    };

    // per-row factors, stabilized by m = leaky(lp)
    __half2 E0, E0p, E1, E1p;
    {
        const float lp0 = g_lp[(bN + i0 + gid)     * Hh + hh];
        const float lp1 = g_lp[(bN + i0 + gid + 8) * Hh + hh];
        const float m0 = fmaxf(lp0, 0.2f * lp0);
        const float m1 = fmaxf(lp1, 0.2f * lp1);
        E0  = __float2half2_rn(ex2f(lp0 - m0));
        E0p = __float2half2_rn(ex2f(0.2f * lp0 - m0));
        E1  = __float2half2_rn(ex2f(lp1 - m1));
        E1p = __float2half2_rn(ex2f(0.2f * lp1 - m1));
    }

    const __half* FFb = g_FF2 + ((size_t)b * Hh + hh) * (Nn / 16) * 32 + tig * 8;
    const char* Hbase = (const char*)g_hT3
        + (size_t)b * NJB * 32768 + (hh * 8 + gid) * 32 + tig * 8;

    float dn0 = 0.f, dn1 = 0.f, dn2 = 0.f, dn3 = 0.f;
    float dd0 = 0.f, dd1 = 0.f, dd2 = 0.f, dd3 = 0.f;
    const uint32_t ONES = 0x3C003C00u;

    // convert mapping: thread t -> row = t>>4, c = t&15 (cols 4c..4c+3)
    const int cv_row = t >> 4;
    const int cv_c   = t & 15;
    const int cv_ks  = cv_c >> 2;
    const uint32_t cv_b0 = cv_row * 32 + ((cv_c & 1) * 2) * 8 + (((cv_c >> 1) & 1)) * 4;
    const int do_tail = copy_adj && (hp == 0);

    if (t == 0) { issue_tile(0); issue_tile(1); issue_tile(2); }

    for (int jb = 0; jb < NJB; ++jb) {
        const int st = jb & 3;
        char* const sFb = smem + SO_F + st * SF_STRIDE;
        char* const sAb = smem + SO_A + (jb & 1) * SA_STRIDE;

        mbar_wait(s2u(&mbar[st]), (jb >> 2) & 1);

        // ---- convert fp32 adj tile -> paired fp16 layout ----
        {
            const float4 v0 = *(const float4*)(sFb + 16 * t);
            const float4 v1 = *(const float4*)(sFb + 16 * t + 4096);
            *(uint32_t*)(sAb + cv_ks * 512 + cv_b0)           = packh2(v0.x, v0.y);
            *(uint32_t*)(sAb + cv_ks * 512 + cv_b0 + 8)       = packh2(v0.z, v0.w);
            *(uint32_t*)(sAb + (cv_ks + 4) * 512 + cv_b0)     = packh2(v1.x, v1.y);
            *(uint32_t*)(sAb + (cv_ks + 4) * 512 + cv_b0 + 8) = packh2(v1.z, v1.w);
        }
        __syncthreads();
        if (t == 0) {
            if (do_tail) {
                asm volatile("fence.proxy.async.shared::cta;" ::: "memory");
                TMA2D_ST(&tmat, jb * 128,      yrow, s2u(sFb));
                TMA2D_ST(&tmat, jb * 128 + 64, yrow, s2u(sFb) + 4096);
                TMA_ST_COMMIT();
                TMA_ST_WAIT(1);
            }
            if (jb + 3 < NJB) issue_tile(jb + 3);
        }

        const char* Hp  = Hbase + (size_t)jb * 32768;
        const char* Ap0 = sAb + gid * 32       + tig * 8;
        const char* Ap1 = sAb + (gid + 8) * 32 + tig * 8;
        const __half* Fj = FFb + jb * 256;

#pragma unroll
        for (int ks = 0; ks < 8; ++ks) {
            const uint4 ff = *(const uint4*)(Fj + ks * 32);
            const uint2 bh = *(const uint2*)(Hp + ks * 4096);
            const uint2 a0 = *(const uint2*)(Ap0 + ks * 512);
            const uint2 a1 = *(const uint2*)(Ap1 + ks * 512);

            const __half2 w0lo = __hmax2(__hmul2(b2h(ff.x), E0),  __hmul2(b2h(ff.z), E0p));
            const __half2 w1lo = __hmax2(__hmul2(b2h(ff.x), E1),  __hmul2(b2h(ff.z), E1p));
            const __half2 w0hi = __hmax2(__hmul2(b2h(ff.y), E0),  __hmul2(b2h(ff.w), E0p));
            const __half2 w1hi = __hmax2(__hmul2(b2h(ff.y), E1),  __hmul2(b2h(ff.w), E1p));

            const uint32_t ra0 = h2b(__hmul2(w0lo, b2h(a0.x)));
            const uint32_t ra1 = h2b(__hmul2(w1lo, b2h(a1.x)));
            const uint32_t ra2 = h2b(__hmul2(w0hi, b2h(a0.y)));
            const uint32_t ra3 = h2b(__hmul2(w1hi, b2h(a1.y)));

            mma16816(dn0, dn1, dn2, dn3, ra0, ra1, ra2, ra3, bh.x, bh.y);
            mma16816(dd0, dd1, dd2, dd3, ra0, ra1, ra2, ra3, ONES, ONES);
        }
    }

    // ---- epilogue: divide and store ----
    {
        const float inv0 = 1.0f / dd0;
        const float inv1 = 1.0f / dd2;
        float2 o0 = make_float2(dn0 * inv0, dn1 * inv0);
        float2 o1 = make_float2(dn2 * inv1, dn3 * inv1);
        *(float2*)(out + (bN + i0 + gid)     * HC + hh * Cc + 2 * tig) = o0;
        *(float2*)(out + (bN + i0 + gid + 8) * HC + hh * Cc + 2 * tig) = o1;
    }

    if (t == 0 && do_tail) TMA_ST_WAIT(0);
}

// ---------------------------------------------------------------
extern "C" void kernel_launch(void* const* d_in, const int* in_sizes, int n_in,
                              void* d_out, int out_size) {
    const float* nf   = (const float*)d_in[0];
    const float* adj  = (const float*)d_in[1];
    const float* W    = (const float*)d_in[2];
    const float* bias = (const float*)d_in[3];
    const float* a    = (const float*)d_in[4];
    float* out = (float*)d_out;

    const long long outel = (long long)Bn * Nn * HC;        // 524288
    const long long adjel = (long long)Bn * Nn * Nn;        // 8388608
    const int copy_adj = ((long long)out_size >= outel + adjel) ? 1 : 0;

    // ---- TMA descriptors ----
    PFN_tmencode pfn = nullptr;
    cudaDriverEntryPointQueryResult qr;
    cudaGetDriverEntryPoint("cuTensorMapEncodeTiled", (void**)&pfn,
                            cudaEnableDefault, &qr);

    CUtensorMap tmaf, tmat;
    {
        cuuint64_t dims[2]    = { (cuuint64_t)Nn, (cuuint64_t)(Bn * Nn) };
        cuuint64_t strides[1] = { (cuuint64_t)Nn * 4 };
        cuuint32_t box[2]     = { 64, 16 };
        cuuint32_t estr[2]    = { 1, 1 };
        pfn(&tmaf, CU_TENSOR_MAP_DATA_TYPE_FLOAT32, 2, (void*)adj, dims, strides,
            box, estr, CU_TENSOR_MAP_INTERLEAVE_NONE, CU_TENSOR_MAP_SWIZZLE_NONE,
            CU_TENSOR_MAP_L2_PROMOTION_L2_128B, CU_TENSOR_MAP_FLOAT_OOB_FILL_NONE);
        // tail destination (same geometry), base = out + outel
        pfn(&tmat, CU_TENSOR_MAP_DATA_TYPE_FLOAT32, 2, (void*)(out + outel),
            dims, strides, box, estr,
            CU_TENSOR_MAP_INTERLEAVE_NONE, CU_TENSOR_MAP_SWIZZLE_NONE,
            CU_TENSOR_MAP_L2_PROMOTION_L2_128B, CU_TENSOR_MAP_FLOAT_OOB_FILL_NONE);
    }

    cudaFuncSetAttribute(k_main, cudaFuncAttributeMaxDynamicSharedMemorySize,
                         SMEM_BYTES);

    k_proj<<<Bn * Nn / 16, 128>>>(nf, W, bias, a);
    k_main<<<Bn * 256, 256, SMEM_BYTES>>>(tmaf, tmat, out, copy_adj);
}